// round 8
// baseline (speedup 1.0000x reference)
#include <cuda_runtime.h>
#include <cuda_fp16.h>
#include <cstdint>

// ============================================================================
// VectorQuantizer — HFMA2 fp16 screen (2x fp32 MAC rate) + exact fp32 verify
//   z [16,256,32,32] f32, emb_w [8192,256] f32
//   out (f32): z_q [16,256,32,32] | loss [1] | min_idx [16,32,32]
//
// Screen: S = sum_k half(z_k) * half(e_k * 2^14), fp16 accumulation in 16-dim
//   HFMA2 chains folded into an fp16 accB (HADD2). d_screen = fmaf(S,-2^-13,zsq).
//   Deterministic per-row bound: eps_r = 4.5e-6 * Sum|z| + 1e-4.
//   Brackets [chunkmin - eps, chunkmin + eps] per (row, 8-code chunk).
// Verify: chunks with L <= min(U) recomputed with the EXACT reference fp32
//   chain (ascending-k fmaf, d = fl(zsq-2dot), first-index ties) — the same
//   passB machinery that scored rel_err = 0 in round 6.
// ============================================================================

#define N_ROWS   16384
#define NE       8192
#define EDIM     256
#define ZQ_SIZE  4194304
#define BETA_F   1.0f
#define C2N      (-1.220703125e-4f)   /* -2^-13 */

__device__ __align__(16) __half g_z16t[EDIM * N_ROWS];   // [k][row]
__device__ __align__(16) __half g_e16t[EDIM * NE];       // [k][code], scaled 2^14
__device__ float  g_zsq[N_ROWS];
__device__ float  g_eps[N_ROWS];
__device__ float  g_cminL[N_ROWS * 1024];                // per 8-code chunk
__device__ float  g_cminU[N_ROWS * 1024];
__device__ int    g_minidx[N_ROWS];
__device__ double g_loss_sum;

__device__ __forceinline__ __half2 u2h2(uint32_t u) {
    __half2 r; *(uint32_t*)&r = u; return r;
}

// ============================================================================
// Preprocessing
// ============================================================================
__global__ void vq_init() { g_loss_sum = 0.0; }

// z [b][k][hw] -> g_z16t[k][b*1024+hw]  (pure index remap, coalesced)
__global__ __launch_bounds__(256) void vq_z16(const float* __restrict__ z) {
    int o = blockIdx.x * 256 + threadIdx.x;
    int k = o >> 14, n = o & 16383;
    int b = n >> 10, hw = n & 1023;
    g_z16t[o] = __float2half_rn(z[(size_t)b * 262144 + (size_t)k * 1024 + hw]);
}

// emb [code][k] -> g_e16t[k][code], scaled by 2^14 (exact pow2)
__global__ __launch_bounds__(256) void vq_e16t(const float* __restrict__ emb) {
    __shared__ float t[32][33];
    const int c0 = blockIdx.x * 32, k0 = blockIdx.y * 32;
    const int tx = threadIdx.x, ty = threadIdx.y;   // (32, 8)
    #pragma unroll
    for (int i = 0; i < 4; ++i)
        t[ty + i * 8][tx] = emb[(size_t)(c0 + ty + i * 8) * 256 + k0 + tx];
    __syncthreads();
    #pragma unroll
    for (int i = 0; i < 4; ++i)
        g_e16t[(size_t)(k0 + ty + i * 8) * NE + c0 + tx] =
            __float2half_rn(t[tx][ty + i * 8] * 16384.0f);
}

// exact ||z||^2 (reference op order) + per-row screen error bound
__global__ __launch_bounds__(256) void vq_zsq_eps(const float* __restrict__ z) {
    const int n = blockIdx.x * 256 + threadIdx.x;
    const int b = n >> 10, hw = n & 1023;
    float s = 0.0f, a = 0.0f;
    for (int k = 0; k < 256; ++k) {
        float v = z[(size_t)b * 262144 + (size_t)k * 1024 + hw];
        s = __fadd_rn(s, __fmul_rn(v, v));
        a += fabsf(v);
    }
    g_zsq[n] = s;
    g_eps[n] = __fmaf_rn(a, 4.5e-6f, 1.0e-4f);
}

// ============================================================================
// Screen: 256 CTAs x (64 rows x 8192 codes). Thread tile 4 rows x 8 codes.
// smem: zs [256 k][PZ half2] (row pairs), es [64 k][PE half2] (codes, dup'd)
// ============================================================================
#define PZ 36      // half2 pitch (72 halfs = 144 B, 16-mult, 36 banks)
#define PE 132     // half2 pitch (528 B, 16-mult, 132 banks)
#define ZS_H2 (256 * PZ)
#define ES_H2 (64 * PE)
#define SCR_SMEM ((ZS_H2 + ES_H2) * 4)   // 70656 B

__global__ __launch_bounds__(256, 2) void vq_screen() {
    extern __shared__ __half2 sh[];
    __half2* zs = sh;              // [k * PZ + rowpair]
    __half2* es = sh + ZS_H2;      // [k * PE + code] duplicated (e,e)
    const int tid = threadIdx.x;
    const int i = tid >> 4;        // row group 0..15 (4 rows each)
    const int j = tid & 15;        // code group 0..15 (8 codes each)
    const int row0 = blockIdx.x * 64;

    // stage zs: 256 k x 64 halfs (128 B per k), coalesced uint4
    #pragma unroll
    for (int it = 0; it < 8; ++it) {
        int f = it * 256 + tid;
        int k = f >> 3, gs = f & 7;
        uint4 v = *(const uint4*)(g_z16t + (size_t)k * N_ROWS + row0 + gs * 8);
        *(uint4*)(zs + k * PZ + gs * 4) = v;
    }

    float zsqv[4], epsv[4];
    #pragma unroll
    for (int r = 0; r < 4; ++r) {
        zsqv[r] = g_zsq[row0 + i * 4 + r];
        epsv[r] = g_eps[row0 + i * 4 + r];
    }

    const __half2 h2z = __float2half2_rn(0.0f);

    for (int ct = 0; ct < 64; ++ct) {
        __half2 accB[2][8];
        #pragma unroll
        for (int rp = 0; rp < 2; ++rp)
            #pragma unroll
            for (int c = 0; c < 8; ++c) accB[rp][c] = h2z;

        for (int ks = 0; ks < 4; ++ks) {
            __syncthreads();   // previous kseg consumers done (also covers zs)
            // stage es: 64 k x 128 codes, duplicated into half2
            #pragma unroll
            for (int it = 0; it < 4; ++it) {
                int f = it * 256 + tid;
                int k = f >> 4, gs = f & 15;
                uint4 v = *(const uint4*)(
                    g_e16t + (size_t)(ks * 64 + k) * NE + ct * 128 + gs * 8);
                uint4 lo, hi;
                lo.x = __byte_perm(v.x, v.x, 0x1010);
                lo.y = __byte_perm(v.x, v.x, 0x3232);
                lo.z = __byte_perm(v.y, v.y, 0x1010);
                lo.w = __byte_perm(v.y, v.y, 0x3232);
                hi.x = __byte_perm(v.z, v.z, 0x1010);
                hi.y = __byte_perm(v.z, v.z, 0x3232);
                hi.z = __byte_perm(v.w, v.w, 0x1010);
                hi.w = __byte_perm(v.w, v.w, 0x3232);
                *(uint4*)(es + k * PE + gs * 8)     = lo;
                *(uint4*)(es + k * PE + gs * 8 + 4) = hi;
            }
            __syncthreads();

            #pragma unroll 1
            for (int seg = 0; seg < 4; ++seg) {   // 4 error-segs of 16 dims
                __half2 acc2[2][8];
                #pragma unroll
                for (int rp = 0; rp < 2; ++rp)
                    #pragma unroll
                    for (int c = 0; c < 8; ++c) acc2[rp][c] = h2z;

                #pragma unroll
                for (int kk = 0; kk < 16; ++kk) {
                    const int k = seg * 16 + kk;
                    uint2 zv = *(const uint2*)(zs + (ks * 64 + k) * PZ + i * 2);
                    __half2 z0 = u2h2(zv.x), z1 = u2h2(zv.y);
                    const __half2* ep = es + k * PE + j * 8;
                    uint4 ea = *(const uint4*)ep;
                    uint4 eb = *(const uint4*)(ep + 4);
                    __half2 e0 = u2h2(ea.x), e1 = u2h2(ea.y);
                    __half2 e2 = u2h2(ea.z), e3 = u2h2(ea.w);
                    __half2 e4 = u2h2(eb.x), e5 = u2h2(eb.y);
                    __half2 e6 = u2h2(eb.z), e7 = u2h2(eb.w);
                    acc2[0][0] = __hfma2(z0, e0, acc2[0][0]);
                    acc2[0][1] = __hfma2(z0, e1, acc2[0][1]);
                    acc2[0][2] = __hfma2(z0, e2, acc2[0][2]);
                    acc2[0][3] = __hfma2(z0, e3, acc2[0][3]);
                    acc2[0][4] = __hfma2(z0, e4, acc2[0][4]);
                    acc2[0][5] = __hfma2(z0, e5, acc2[0][5]);
                    acc2[0][6] = __hfma2(z0, e6, acc2[0][6]);
                    acc2[0][7] = __hfma2(z0, e7, acc2[0][7]);
                    acc2[1][0] = __hfma2(z1, e0, acc2[1][0]);
                    acc2[1][1] = __hfma2(z1, e1, acc2[1][1]);
                    acc2[1][2] = __hfma2(z1, e2, acc2[1][2]);
                    acc2[1][3] = __hfma2(z1, e3, acc2[1][3]);
                    acc2[1][4] = __hfma2(z1, e4, acc2[1][4]);
                    acc2[1][5] = __hfma2(z1, e5, acc2[1][5]);
                    acc2[1][6] = __hfma2(z1, e6, acc2[1][6]);
                    acc2[1][7] = __hfma2(z1, e7, acc2[1][7]);
                }
                #pragma unroll
                for (int rp = 0; rp < 2; ++rp)
                    #pragma unroll
                    for (int c = 0; c < 8; ++c)
                        accB[rp][c] = __hadd2(accB[rp][c], acc2[rp][c]);
            }
        }

        // epilogue: d per code, min over this thread's 8 codes, bracket store
        float dmin[4] = {3.4e38f, 3.4e38f, 3.4e38f, 3.4e38f};
        #pragma unroll
        for (int c = 0; c < 8; ++c) {
            #pragma unroll
            for (int rp = 0; rp < 2; ++rp) {
                float2 s = __half22float2(accB[rp][c]);
                float d0 = __fmaf_rn(s.x, C2N, zsqv[rp * 2]);
                float d1 = __fmaf_rn(s.y, C2N, zsqv[rp * 2 + 1]);
                dmin[rp * 2]     = fminf(dmin[rp * 2], d0);
                dmin[rp * 2 + 1] = fminf(dmin[rp * 2 + 1], d1);
            }
        }
        #pragma unroll
        for (int r = 0; r < 4; ++r) {
            size_t o = (size_t)(row0 + i * 4 + r) * 1024 + ct * 16 + j;
            g_cminL[o] = dmin[r] - epsv[r];
            g_cminU[o] = dmin[r] + epsv[r];
        }
    }
}

// ============================================================================
// Pass B: exact fp32 verify (validated bit-exact in round 6). thr = min(U).
// ============================================================================
#define PB_SMEM (4 * 32 * 257 * 4 + 4 * 256 * 4 + 4 * 4 * 4)

__global__ __launch_bounds__(128) void vq_passb(
    const float* __restrict__ z,
    const float* __restrict__ emb,
    float* __restrict__ out_idx_f)
{
    extern __shared__ float smf[];
    const int w = threadIdx.x >> 5, lane = threadIdx.x & 31;
    float* esm = smf + w * (32 * 257);
    float* zsm = smf + 4 * (32 * 257) + w * 256;
    int*   slots = (int*)(smf + 4 * (32 * 257) + 4 * 256) + w * 4;
    const int r = blockIdx.x * 4 + w;
    const int b = r >> 10, hw = r & 1023;

    const float* cU = g_cminU + (size_t)r * 1024;
    const float* cL = g_cminL + (size_t)r * 1024;

    float mu = 3.4e38f;
    for (int g = 0; g < 32; ++g)
        mu = fminf(mu, cU[g * 32 + lane]);
    #pragma unroll
    for (int off = 16; off > 0; off >>= 1)
        mu = fminf(mu, __shfl_xor_sync(0xffffffffu, mu, off));
    const float thr = mu;

    for (int k = lane; k < 256; k += 32)
        zsm[k] = z[(size_t)b * 262144 + (size_t)k * 1024 + hw];
    __syncwarp();
    const float zsqv = g_zsq[r];

    float bd = 3.4e38f;
    int   bi = 0x7fffffff;
    int   ns = 0;

    auto flush = [&](int n) {
        __syncwarp();
        for (int t = lane; t < n * 8 * 256; t += 32) {
            int rr = t >> 8, k = t & 255;
            int code = slots[rr >> 3] * 8 + (rr & 7);
            esm[rr * 257 + k] = emb[(size_t)code * 256 + k];
        }
        __syncwarp();
        if (lane < n * 8) {
            float dacc = 0.0f;
            const float* ep = esm + lane * 257;
            for (int k = 0; k < 256; ++k)
                dacc = __fmaf_rn(zsm[k], ep[k], dacc);
            float d = __fmaf_rn(-2.0f, dacc, zsqv);
            int idx = slots[lane >> 3] * 8 + (lane & 7);
            if (d < bd || (d == bd && idx < bi)) { bd = d; bi = idx; }
        }
        __syncwarp();
    };

    for (int g = 0; g < 32; ++g) {
        float lv = cL[g * 32 + lane];
        unsigned m = __ballot_sync(0xffffffffu, lv <= thr);
        while (m) {
            int src = __ffs(m) - 1;
            m &= m - 1;
            if (lane == 0) slots[ns] = g * 32 + src;
            ns++;
            if (ns == 4) { flush(4); ns = 0; }
        }
    }
    if (ns) flush(ns);

    #pragma unroll
    for (int off = 16; off > 0; off >>= 1) {
        float od = __shfl_down_sync(0xffffffffu, bd, off);
        int   oi = __shfl_down_sync(0xffffffffu, bi, off);
        if (od < bd || (od == bd && oi < bi)) { bd = od; bi = oi; }
    }
    if (lane == 0) {
        g_minidx[r]  = bi;
        out_idx_f[r] = (float)bi;
    }
}

// ============================================================================
// Output: straight-through z_q + loss (bit-identical to passing kernels)
// ============================================================================
__global__ __launch_bounds__(256) void vq_out_kernel(
    const float* __restrict__ z,
    const float* __restrict__ emb,
    float* __restrict__ out)
{
    const int o = blockIdx.x * 256 + threadIdx.x;
    const int c = (o >> 10) & 255;
    const int n = ((o >> 18) << 10) | (o & 1023);

    const int idx = g_minidx[n];
    const float zv = z[o];
    const float ev = __ldg(&emb[(size_t)idx * 256 + c]);
    const float diff = __fsub_rn(ev, zv);
    out[o] = __fadd_rn(zv, diff);
    const float sq = __fmul_rn(diff, diff);

    double v = (double)sq;
    #pragma unroll
    for (int off = 16; off > 0; off >>= 1)
        v += __shfl_down_sync(0xffffffffu, v, off);
    __shared__ double ws[8];
    if ((threadIdx.x & 31) == 0) ws[threadIdx.x >> 5] = v;
    __syncthreads();
    if (threadIdx.x == 0) {
        double s = 0.0;
        #pragma unroll
        for (int wv = 0; wv < 8; ++wv) s += ws[wv];
        atomicAdd(&g_loss_sum, s);
    }
}

__global__ void vq_finalize_kernel(float* __restrict__ out) {
    float m = (float)(g_loss_sum / (double)ZQ_SIZE);
    out[ZQ_SIZE] = __fadd_rn(__fmul_rn(BETA_F, m), m);
}

// ============================================================================
extern "C" void kernel_launch(void* const* d_in, const int* in_sizes, int n_in,
                              void* d_out, int out_size)
{
    const float* z   = (const float*)d_in[0];
    const float* emb = (const float*)d_in[1];
    float* out = (float*)d_out;

    cudaFuncSetAttribute(vq_screen,
                         cudaFuncAttributeMaxDynamicSharedMemorySize, SCR_SMEM);
    cudaFuncSetAttribute(vq_passb,
                         cudaFuncAttributeMaxDynamicSharedMemorySize, PB_SMEM);

    vq_init<<<1, 1>>>();
    vq_e16t<<<dim3(256, 8), dim3(32, 8)>>>(emb);
    vq_z16<<<ZQ_SIZE / 256, 256>>>(z);
    vq_zsq_eps<<<N_ROWS / 256, 256>>>(z);

    vq_screen<<<256, 256, SCR_SMEM>>>();

    vq_passb<<<N_ROWS / 4, 128, PB_SMEM>>>(z, emb, out + ZQ_SIZE + 1);

    vq_out_kernel<<<ZQ_SIZE / 256, 256>>>(z, emb, out);
    vq_finalize_kernel<<<1, 1>>>(out);
}

// round 10
// speedup vs baseline: 1.0018x; 1.0018x over previous
#include <cuda_runtime.h>
#include <cuda_fp16.h>
#include <cstdint>

// ============================================================================
// VectorQuantizer — HFMA2 fp16 screen (rt2 fma-pipe, 2 MACs/instr) + exact
// fp32 verify. Numerics identical to round-7 (rel_err 0.0); engine fixed:
// no address-taken locals (the round-7 u2h2 bitcast demoted operands to
// local memory -> 15x slowdown). All smem loads via POD half2 structs.
// (Round-9 submission re-benched: previous run died to a container error.)
// ============================================================================

#define N_ROWS   16384
#define NE       8192
#define EDIM     256
#define ZQ_SIZE  4194304
#define BETA_F   1.0f
#define C2N      (-1.220703125e-4f)   /* -2^-13 */

__device__ __align__(16) __half g_z16t[EDIM * N_ROWS];   // [k][row]
__device__ __align__(16) __half g_e16t[EDIM * NE];       // [k][code], scaled 2^14
__device__ float  g_zsq[N_ROWS];
__device__ float  g_eps[N_ROWS];
__device__ float  g_cminL[N_ROWS * 1024];                // per 8-code chunk
__device__ float  g_cminU[N_ROWS * 1024];
__device__ int    g_minidx[N_ROWS];
__device__ double g_loss_sum;

struct H2x2 { __half2 x, y; };            // 8 B  -> LDS.64
struct H2x4 { __half2 x, y, z, w; };      // 16 B -> LDS.128

// ============================================================================
// Preprocessing
// ============================================================================
__global__ void vq_init() { g_loss_sum = 0.0; }

__global__ __launch_bounds__(256) void vq_z16(const float* __restrict__ z) {
    int o = blockIdx.x * 256 + threadIdx.x;
    int k = o >> 14, n = o & 16383;
    int b = n >> 10, hw = n & 1023;
    g_z16t[o] = __float2half_rn(z[(size_t)b * 262144 + (size_t)k * 1024 + hw]);
}

__global__ __launch_bounds__(256) void vq_e16t(const float* __restrict__ emb) {
    __shared__ float t[32][33];
    const int c0 = blockIdx.x * 32, k0 = blockIdx.y * 32;
    const int tx = threadIdx.x, ty = threadIdx.y;   // (32, 8)
    #pragma unroll
    for (int i = 0; i < 4; ++i)
        t[ty + i * 8][tx] = emb[(size_t)(c0 + ty + i * 8) * 256 + k0 + tx];
    __syncthreads();
    #pragma unroll
    for (int i = 0; i < 4; ++i)
        g_e16t[(size_t)(k0 + ty + i * 8) * NE + c0 + tx] =
            __float2half_rn(t[tx][ty + i * 8] * 16384.0f);
}

__global__ __launch_bounds__(256) void vq_zsq_eps(const float* __restrict__ z) {
    const int n = blockIdx.x * 256 + threadIdx.x;
    const int b = n >> 10, hw = n & 1023;
    float s = 0.0f, a = 0.0f;
    for (int k = 0; k < 256; ++k) {
        float v = z[(size_t)b * 262144 + (size_t)k * 1024 + hw];
        s = __fadd_rn(s, __fmul_rn(v, v));
        a += fabsf(v);
    }
    g_zsq[n] = s;
    g_eps[n] = __fmaf_rn(a, 4.5e-6f, 1.0e-4f);
}

// ============================================================================
// Screen: 256 CTAs x (64 rows x 8192 codes). Thread tile 4 rows x 8 codes.
// smem: zs [256 k][36 half2] (row pairs), es [64 k][132 half2] (codes dup'd)
// ============================================================================
#define PZ 36
#define PE 132
#define ZS_H2 (256 * PZ)
#define ES_H2 (64 * PE)
#define SCR_SMEM ((ZS_H2 + ES_H2) * 4)   // 70656 B

__global__ __launch_bounds__(256, 2) void vq_screen() {
    extern __shared__ __half2 sh[];
    __half2* zs = sh;              // [k * PZ + rowpair]
    __half2* es = sh + ZS_H2;      // [k * PE + code] duplicated (e,e)
    const int tid = threadIdx.x;
    const int i = tid >> 4;        // row group 0..15 (4 rows)
    const int j = tid & 15;        // code group 0..15 (8 codes)
    const int row0 = blockIdx.x * 64;

    // stage zs once: 256 k x 64 halfs, coalesced
    #pragma unroll
    for (int it = 0; it < 8; ++it) {
        int f = it * 256 + tid;
        int k = f >> 3, gs = f & 7;
        uint4 v = *(const uint4*)(g_z16t + (size_t)k * N_ROWS + row0 + gs * 8);
        *(uint4*)(zs + k * PZ + gs * 4) = v;
    }

    float zsqv[4], epsv[4];
    #pragma unroll
    for (int r = 0; r < 4; ++r) {
        zsqv[r] = g_zsq[row0 + i * 4 + r];
        epsv[r] = g_eps[row0 + i * 4 + r];
    }

    // prefetch regs for (ct=0, ks=0)
    uint4 pre[4];
    #pragma unroll
    for (int it = 0; it < 4; ++it) {
        int f = it * 256 + tid;
        int k = f >> 4, gs = f & 15;
        pre[it] = *(const uint4*)(g_e16t + (size_t)k * NE + gs * 8);
    }

    const __half2 h2z = __float2half2_rn(0.0f);

    for (int ct = 0; ct < 64; ++ct) {
        __half2 accB[2][8];
        #pragma unroll
        for (int rp = 0; rp < 2; ++rp)
            #pragma unroll
            for (int c = 0; c < 8; ++c) accB[rp][c] = h2z;

        for (int ks = 0; ks < 4; ++ks) {
            __syncthreads();   // previous slice's consumers done
            // dup-store prefetched slice into es
            #pragma unroll
            for (int it = 0; it < 4; ++it) {
                int f = it * 256 + tid;
                int k = f >> 4, gs = f & 15;
                uint4 v = pre[it];
                uint4 lo, hi;
                lo.x = __byte_perm(v.x, v.x, 0x1010);
                lo.y = __byte_perm(v.x, v.x, 0x3232);
                lo.z = __byte_perm(v.y, v.y, 0x1010);
                lo.w = __byte_perm(v.y, v.y, 0x3232);
                hi.x = __byte_perm(v.z, v.z, 0x1010);
                hi.y = __byte_perm(v.z, v.z, 0x3232);
                hi.z = __byte_perm(v.w, v.w, 0x1010);
                hi.w = __byte_perm(v.w, v.w, 0x3232);
                *(uint4*)(es + k * PE + gs * 8)     = lo;
                *(uint4*)(es + k * PE + gs * 8 + 4) = hi;
            }
            // prefetch next slice (latency hides behind this slice's compute)
            {
                int nks = (ks == 3) ? 0 : ks + 1;
                int nct = (ks == 3) ? ct + 1 : ct;
                if (nct < 64) {
                    #pragma unroll
                    for (int it = 0; it < 4; ++it) {
                        int f = it * 256 + tid;
                        int k = f >> 4, gs = f & 15;
                        pre[it] = *(const uint4*)(
                            g_e16t + (size_t)(nks * 64 + k) * NE + nct * 128 + gs * 8);
                    }
                }
            }
            __syncthreads();

            #pragma unroll 1
            for (int seg = 0; seg < 4; ++seg) {   // 16-dim fp16 chains
                __half2 acc2[2][8];
                #pragma unroll
                for (int rp = 0; rp < 2; ++rp)
                    #pragma unroll
                    for (int c = 0; c < 8; ++c) acc2[rp][c] = h2z;

                #pragma unroll
                for (int kk = 0; kk < 16; ++kk) {
                    const int k = seg * 16 + kk;
                    H2x2 zv = *(const H2x2*)(zs + (ks * 64 + k) * PZ + i * 2);
                    const __half2* ep = es + k * PE + j * 8;
                    H2x4 ea = *(const H2x4*)ep;
                    H2x4 eb = *(const H2x4*)(ep + 4);
                    acc2[0][0] = __hfma2(zv.x, ea.x, acc2[0][0]);
                    acc2[0][1] = __hfma2(zv.x, ea.y, acc2[0][1]);
                    acc2[0][2] = __hfma2(zv.x, ea.z, acc2[0][2]);
                    acc2[0][3] = __hfma2(zv.x, ea.w, acc2[0][3]);
                    acc2[0][4] = __hfma2(zv.x, eb.x, acc2[0][4]);
                    acc2[0][5] = __hfma2(zv.x, eb.y, acc2[0][5]);
                    acc2[0][6] = __hfma2(zv.x, eb.z, acc2[0][6]);
                    acc2[0][7] = __hfma2(zv.x, eb.w, acc2[0][7]);
                    acc2[1][0] = __hfma2(zv.y, ea.x, acc2[1][0]);
                    acc2[1][1] = __hfma2(zv.y, ea.y, acc2[1][1]);
                    acc2[1][2] = __hfma2(zv.y, ea.z, acc2[1][2]);
                    acc2[1][3] = __hfma2(zv.y, ea.w, acc2[1][3]);
                    acc2[1][4] = __hfma2(zv.y, eb.x, acc2[1][4]);
                    acc2[1][5] = __hfma2(zv.y, eb.y, acc2[1][5]);
                    acc2[1][6] = __hfma2(zv.y, eb.z, acc2[1][6]);
                    acc2[1][7] = __hfma2(zv.y, eb.w, acc2[1][7]);
                }
                #pragma unroll
                for (int rp = 0; rp < 2; ++rp)
                    #pragma unroll
                    for (int c = 0; c < 8; ++c)
                        accB[rp][c] = __hadd2(accB[rp][c], acc2[rp][c]);
            }
        }

        // epilogue: d per code, min over this thread's 8 codes, bracket store
        float dmin[4] = {3.4e38f, 3.4e38f, 3.4e38f, 3.4e38f};
        #pragma unroll
        for (int c = 0; c < 8; ++c) {
            #pragma unroll
            for (int rp = 0; rp < 2; ++rp) {
                float2 s = __half22float2(accB[rp][c]);
                float d0 = __fmaf_rn(s.x, C2N, zsqv[rp * 2]);
                float d1 = __fmaf_rn(s.y, C2N, zsqv[rp * 2 + 1]);
                dmin[rp * 2]     = fminf(dmin[rp * 2], d0);
                dmin[rp * 2 + 1] = fminf(dmin[rp * 2 + 1], d1);
            }
        }
        #pragma unroll
        for (int r = 0; r < 4; ++r) {
            size_t o = (size_t)(row0 + i * 4 + r) * 1024 + ct * 16 + j;
            g_cminL[o] = dmin[r] - epsv[r];
            g_cminU[o] = dmin[r] + epsv[r];
        }
    }
}

// ============================================================================
// Pass B: exact fp32 verify (validated rel_err 0 in rounds 6-8)
// ============================================================================
#define PB_SMEM (4 * 32 * 257 * 4 + 4 * 256 * 4 + 4 * 4 * 4)

__global__ __launch_bounds__(128) void vq_passb(
    const float* __restrict__ z,
    const float* __restrict__ emb,
    float* __restrict__ out_idx_f)
{
    extern __shared__ float smf[];
    const int w = threadIdx.x >> 5, lane = threadIdx.x & 31;
    float* esm = smf + w * (32 * 257);
    float* zsm = smf + 4 * (32 * 257) + w * 256;
    int*   slots = (int*)(smf + 4 * (32 * 257) + 4 * 256) + w * 4;
    const int r = blockIdx.x * 4 + w;
    const int b = r >> 10, hw = r & 1023;

    const float* cU = g_cminU + (size_t)r * 1024;
    const float* cL = g_cminL + (size_t)r * 1024;

    float mu = 3.4e38f;
    for (int g = 0; g < 32; ++g)
        mu = fminf(mu, cU[g * 32 + lane]);
    #pragma unroll
    for (int off = 16; off > 0; off >>= 1)
        mu = fminf(mu, __shfl_xor_sync(0xffffffffu, mu, off));
    const float thr = mu;

    for (int k = lane; k < 256; k += 32)
        zsm[k] = z[(size_t)b * 262144 + (size_t)k * 1024 + hw];
    __syncwarp();
    const float zsqv = g_zsq[r];

    float bd = 3.4e38f;
    int   bi = 0x7fffffff;
    int   ns = 0;

    auto flush = [&](int n) {
        __syncwarp();
        for (int t = lane; t < n * 8 * 256; t += 32) {
            int rr = t >> 8, k = t & 255;
            int code = slots[rr >> 3] * 8 + (rr & 7);
            esm[rr * 257 + k] = emb[(size_t)code * 256 + k];
        }
        __syncwarp();
        if (lane < n * 8) {
            float dacc = 0.0f;
            const float* ep = esm + lane * 257;
            for (int k = 0; k < 256; ++k)
                dacc = __fmaf_rn(zsm[k], ep[k], dacc);
            float d = __fmaf_rn(-2.0f, dacc, zsqv);
            int idx = slots[lane >> 3] * 8 + (lane & 7);
            if (d < bd || (d == bd && idx < bi)) { bd = d; bi = idx; }
        }
        __syncwarp();
    };

    for (int g = 0; g < 32; ++g) {
        float lv = cL[g * 32 + lane];
        unsigned m = __ballot_sync(0xffffffffu, lv <= thr);
        while (m) {
            int src = __ffs(m) - 1;
            m &= m - 1;
            if (lane == 0) slots[ns] = g * 32 + src;
            ns++;
            if (ns == 4) { flush(4); ns = 0; }
        }
    }
    if (ns) flush(ns);

    #pragma unroll
    for (int off = 16; off > 0; off >>= 1) {
        float od = __shfl_down_sync(0xffffffffu, bd, off);
        int   oi = __shfl_down_sync(0xffffffffu, bi, off);
        if (od < bd || (od == bd && oi < bi)) { bd = od; bi = oi; }
    }
    if (lane == 0) {
        g_minidx[r]  = bi;
        out_idx_f[r] = (float)bi;
    }
}

// ============================================================================
// Output: straight-through z_q + loss (bit-identical to passing kernels)
// ============================================================================
__global__ __launch_bounds__(256) void vq_out_kernel(
    const float* __restrict__ z,
    const float* __restrict__ emb,
    float* __restrict__ out)
{
    const int o = blockIdx.x * 256 + threadIdx.x;
    const int c = (o >> 10) & 255;
    const int n = ((o >> 18) << 10) | (o & 1023);

    const int idx = g_minidx[n];
    const float zv = z[o];
    const float ev = __ldg(&emb[(size_t)idx * 256 + c]);
    const float diff = __fsub_rn(ev, zv);
    out[o] = __fadd_rn(zv, diff);
    const float sq = __fmul_rn(diff, diff);

    double v = (double)sq;
    #pragma unroll
    for (int off = 16; off > 0; off >>= 1)
        v += __shfl_down_sync(0xffffffffu, v, off);
    __shared__ double ws[8];
    if ((threadIdx.x & 31) == 0) ws[threadIdx.x >> 5] = v;
    __syncthreads();
    if (threadIdx.x == 0) {
        double s = 0.0;
        #pragma unroll
        for (int wv = 0; wv < 8; ++wv) s += ws[wv];
        atomicAdd(&g_loss_sum, s);
    }
}

__global__ void vq_finalize_kernel(float* __restrict__ out) {
    float m = (float)(g_loss_sum / (double)ZQ_SIZE);
    out[ZQ_SIZE] = __fadd_rn(__fmul_rn(BETA_F, m), m);
}

// ============================================================================
extern "C" void kernel_launch(void* const* d_in, const int* in_sizes, int n_in,
                              void* d_out, int out_size)
{
    const float* z   = (const float*)d_in[0];
    const float* emb = (const float*)d_in[1];
    float* out = (float*)d_out;

    cudaFuncSetAttribute(vq_screen,
                         cudaFuncAttributeMaxDynamicSharedMemorySize, SCR_SMEM);
    cudaFuncSetAttribute(vq_passb,
                         cudaFuncAttributeMaxDynamicSharedMemorySize, PB_SMEM);

    vq_init<<<1, 1>>>();
    vq_e16t<<<dim3(256, 8), dim3(32, 8)>>>(emb);
    vq_z16<<<ZQ_SIZE / 256, 256>>>(z);
    vq_zsq_eps<<<N_ROWS / 256, 256>>>(z);

    vq_screen<<<256, 256, SCR_SMEM>>>();

    vq_passb<<<N_ROWS / 4, 128, PB_SMEM>>>(z, emb, out + ZQ_SIZE + 1);

    vq_out_kernel<<<ZQ_SIZE / 256, 256>>>(z, emb, out);
    vq_finalize_kernel<<<1, 1>>>(out);
}

// round 11
// speedup vs baseline: 5.0814x; 5.0723x over previous
#include <cuda_runtime.h>
#include <cuda_fp16.h>
#include <cstdint>

// ============================================================================
// VectorQuantizer hybrid: HMMA screen (codes 4096..8191) running CONCURRENTLY
// with exact-FFMA argmin (codes 0..4095) in the same warps — tests fma-pipe +
// tensor-pipe additivity on sm_103a. Exact fp32 verify (passB) on HMMA side,
// exact merge. All fragment maps / exact chains reused from kernels that
// previously scored rel_err = 0 (rounds 1, 4, 6).
// ============================================================================

#define N_ROWS   16384
#define NE       8192
#define EDIM     256
#define ZQ_SIZE  4194304
#define BETA_F   1.0f
#define C2N      (-1.220703125e-4f)   /* -2^-13: d = fmaf(S, C2N, zsq) */
#define EPS      2.0e-4f              /* screen bound 7.4e-5, 2.7x slack */

__device__ __align__(16) __half g_z16[N_ROWS * EDIM];   // [row][k]
__device__ __align__(16) __half g_e16[NE * EDIM];       // [code][k], * 2^14
__device__ float  g_zsq[N_ROWS];
__device__ float  g_cminL[N_ROWS * 1024];               // high half (512..1023)
__device__ float  g_cminU[N_ROWS * 1024];
__device__ float  g_lowd[N_ROWS];
__device__ int    g_lowi[N_ROWS];
__device__ int    g_minidx[N_ROWS];
__device__ double g_loss_sum;

__device__ __forceinline__ uint32_t smem_u32(const void* p) {
    uint32_t a;
    asm("{ .reg .u64 t; cvta.to.shared.u64 t, %1; cvt.u32.u64 %0, t; }" : "=r"(a) : "l"(p));
    return a;
}
__device__ __forceinline__ void ldsm_x4(uint32_t r[4], uint32_t addr) {
    asm volatile("ldmatrix.sync.aligned.m8n8.x4.shared.b16 {%0,%1,%2,%3}, [%4];"
                 : "=r"(r[0]), "=r"(r[1]), "=r"(r[2]), "=r"(r[3]) : "r"(addr));
}
__device__ __forceinline__ void mma16816(float c[4], const uint32_t a[4], const uint32_t b[2]) {
    asm volatile("mma.sync.aligned.m16n8k16.row.col.f32.f16.f16.f32 "
                 "{%0,%1,%2,%3}, {%4,%5,%6,%7}, {%8,%9}, {%0,%1,%2,%3};"
                 : "+f"(c[0]), "+f"(c[1]), "+f"(c[2]), "+f"(c[3])
                 : "r"(a[0]), "r"(a[1]), "r"(a[2]), "r"(a[3]), "r"(b[0]), "r"(b[1]));
}

// ============================================================================
// Preprocessing
// ============================================================================
__global__ void vq_init() { g_loss_sum = 0.0; }

__global__ __launch_bounds__(256) void vq_e16(const float* __restrict__ emb) {
    int i = blockIdx.x * 256 + threadIdx.x;
    g_e16[i] = __float2half_rn(emb[i] * 16384.0f);   // exact pow2 scale
}

// z [b][k][hw] -> g_z16[row = b*1024+hw][k] (validated round 4)
__global__ __launch_bounds__(256) void vq_z16k(const float* __restrict__ z) {
    __shared__ float t[32][33];
    const int b = blockIdx.z, k0 = blockIdx.y * 32, hw0 = blockIdx.x * 32;
    const int tx = threadIdx.x, ty = threadIdx.y;   // (32, 8)
    #pragma unroll
    for (int i = 0; i < 4; ++i) {
        int kl = ty + i * 8;
        t[kl][tx] = z[(size_t)b * 262144 + (size_t)(k0 + kl) * 1024 + hw0 + tx];
    }
    __syncthreads();
    #pragma unroll
    for (int i = 0; i < 4; ++i) {
        int hwl = ty + i * 8;
        g_z16[((size_t)b * 1024 + hw0 + hwl) * 256 + k0 + tx] = __float2half_rn(t[tx][hwl]);
    }
}

// exact ||z||^2, reference op order (validated round 1)
__global__ __launch_bounds__(256) void vq_zsq(const float* __restrict__ z) {
    const int n = blockIdx.x * 256 + threadIdx.x;
    const int b = n >> 10, hw = n & 1023;
    float s = 0.0f;
    for (int k = 0; k < 256; ++k) {
        float v = z[(size_t)b * 262144 + (size_t)k * 1024 + hw];
        s = __fadd_rn(s, __fmul_rn(v, v));
    }
    g_zsq[n] = s;
}

// ============================================================================
// Hybrid kernel: 256 CTAs x 64 rows, 256 threads (8 warps).
//  HMMA: wm = warp&3 -> 16 rows; wn = warp>>2 -> 64 of the 128-code tile.
//  FFMA: i = tid>>4 -> 4 rows; j = tid&15 -> 8 of the 128-code chunk.
// smem (bytes): zs f32 [256][68] @0 (69632) | z16 [64][264] @69632 (33792) |
//   b16 [128][40] @103424 (10240) | es f32 [32][132] @113664 (16896) |
//   zsq[64] @130560 | red_d @130816 | red_i @134912 | total 139008
// ============================================================================
#define ZS_OFF   0
#define Z16_OFF  69632
#define B16_OFF  103424
#define ES_OFF   113664
#define ZSQ_OFF  130560
#define REDD_OFF 130816
#define REDI_OFF 134912
#define HYB_SMEM 139008

__global__ __launch_bounds__(256, 1) void vq_hybrid(
    const float* __restrict__ z,
    const float* __restrict__ emb)
{
    extern __shared__ char sm[];
    float*  zs    = (float*)(sm + ZS_OFF);     // [k*68 + row]
    __half* z16s  = (__half*)(sm + Z16_OFF);   // [row*264 + k]
    __half* b16s  = (__half*)(sm + B16_OFF);   // [code*40 + klocal]
    float*  es    = (float*)(sm + ES_OFF);     // [klocal*132 + code]
    float*  zsq_s = (float*)(sm + ZSQ_OFF);
    float*  red_d = (float*)(sm + REDD_OFF);
    int*    red_i = (int*)(sm + REDI_OFF);

    const int tid = threadIdx.x;
    const int warp = tid >> 5, lane = tid & 31;
    const int wm = warp & 3, wn = warp >> 2;
    const int i = tid >> 4, j = tid & 15;
    const int row0 = blockIdx.x * 64;
    const int b = row0 >> 10, hw0 = row0 & 1023;

    // ---- stage zs fp32 [k][row] ----
    #pragma unroll
    for (int it = 0; it < 16; ++it) {
        int f = it * 256 + tid;
        int k = f >> 4, r4 = (f & 15) * 4;
        float4 v = *(const float4*)(z + (size_t)b * 262144 + (size_t)k * 1024 + hw0 + r4);
        *(float4*)(zs + k * 68 + r4) = v;
    }
    // ---- stage z16 A-tile [row][k] ----
    #pragma unroll
    for (int it = 0; it < 8; ++it) {
        int f = it * 256 + tid;
        int r = f >> 5, ko = (f & 31) * 8;
        uint4 v = *(const uint4*)(g_z16 + (size_t)(row0 + r) * 256 + ko);
        *(uint4*)(z16s + r * 264 + ko) = v;
    }
    if (tid < 64) zsq_s[tid] = g_zsq[row0 + tid];

    const uint32_t sb = smem_u32(sm);
    const uint32_t aBase = sb + Z16_OFF
        + (uint32_t)(wm * 16 + (lane & 15)) * 528 + (uint32_t)(lane >> 4) * 16;
    const uint32_t bBase = sb + B16_OFF
        + (uint32_t)(wn * 64 + ((lane >> 4) << 3) + (lane & 7)) * 80
        + (uint32_t)((lane >> 3) & 1) * 16;

    float bd[4];
    int   bi[4];
    #pragma unroll
    for (int r = 0; r < 4; ++r) { bd[r] = 3.4e38f; bi[r] = 0; }

    const int rA = wm * 16 + (lane >> 2);

    for (int ct = 0; ct < 32; ++ct) {
        float facc[8][4];   // HMMA accumulators (8 nt x 4)
        float cacc[4][8];   // FFMA accumulators (4 rows x 8 codes)
        #pragma unroll
        for (int nt = 0; nt < 8; ++nt)
            #pragma unroll
            for (int q = 0; q < 4; ++q) facc[nt][q] = 0.0f;
        #pragma unroll
        for (int r = 0; r < 4; ++r)
            #pragma unroll
            for (int c = 0; c < 8; ++c) cacc[r][c] = 0.0f;

        for (int kc = 0; kc < 8; ++kc) {
            __syncthreads();
            // stage b16 slice: high codes 4096+ct*128, k = kc*32..+31
            #pragma unroll
            for (int it = 0; it < 2; ++it) {
                int f = it * 256 + tid;
                int c = f >> 2, ko = (f & 3) * 8;
                uint4 v = *(const uint4*)(
                    g_e16 + (size_t)(4096 + ct * 128 + c) * 256 + kc * 32 + ko);
                *(uint4*)(b16s + c * 40 + ko) = v;
            }
            // stage es fp32 slice: low codes ct*128, k = kc*32..+31
            #pragma unroll
            for (int it = 0; it < 4; ++it) {
                int f = it * 256 + tid;
                int c = f >> 3, kq = (f & 7) * 4;
                float4 v = *(const float4*)(
                    emb + (size_t)(ct * 128 + c) * 256 + kc * 32 + kq);
                es[(kq + 0) * 132 + c] = v.x;
                es[(kq + 1) * 132 + c] = v.y;
                es[(kq + 2) * 132 + c] = v.z;
                es[(kq + 3) * 132 + c] = v.w;
            }
            __syncthreads();

            #pragma unroll
            for (int ks = 0; ks < 2; ++ks) {
                // ---- HMMA batch: 1 ldsm A + 4 ldsm B + 8 mma ----
                uint32_t a[4];
                ldsm_x4(a, aBase + (uint32_t)(kc * 64 + ks * 32));
                uint32_t bb[8][2];
                #pragma unroll
                for (int np = 0; np < 4; ++np) {
                    uint32_t r4[4];
                    ldsm_x4(r4, bBase + (uint32_t)(np * (16 * 80) + ks * 32));
                    bb[2 * np][0] = r4[0]; bb[2 * np][1] = r4[1];
                    bb[2 * np + 1][0] = r4[2]; bb[2 * np + 1][1] = r4[3];
                }
                #pragma unroll
                for (int nt = 0; nt < 8; ++nt)
                    mma16816(facc[nt], a, bb[nt]);

                // ---- FFMA block: 16 kk (tensor unit drains concurrently) ----
                #pragma unroll
                for (int kk = 0; kk < 16; ++kk) {
                    const int klq = ks * 16 + kk;            // k within slice
                    const int kg  = kc * 32 + klq;           // k global
                    float4 zr = *(const float4*)(zs + kg * 68 + i * 4);
                    const float* ep = es + klq * 132 + j * 8;
                    float4 e0 = *(const float4*)ep;
                    float4 e1 = *(const float4*)(ep + 4);
                    cacc[0][0] = __fmaf_rn(zr.x, e0.x, cacc[0][0]);
                    cacc[0][1] = __fmaf_rn(zr.x, e0.y, cacc[0][1]);
                    cacc[0][2] = __fmaf_rn(zr.x, e0.z, cacc[0][2]);
                    cacc[0][3] = __fmaf_rn(zr.x, e0.w, cacc[0][3]);
                    cacc[0][4] = __fmaf_rn(zr.x, e1.x, cacc[0][4]);
                    cacc[0][5] = __fmaf_rn(zr.x, e1.y, cacc[0][5]);
                    cacc[0][6] = __fmaf_rn(zr.x, e1.z, cacc[0][6]);
                    cacc[0][7] = __fmaf_rn(zr.x, e1.w, cacc[0][7]);
                    cacc[1][0] = __fmaf_rn(zr.y, e0.x, cacc[1][0]);
                    cacc[1][1] = __fmaf_rn(zr.y, e0.y, cacc[1][1]);
                    cacc[1][2] = __fmaf_rn(zr.y, e0.z, cacc[1][2]);
                    cacc[1][3] = __fmaf_rn(zr.y, e0.w, cacc[1][3]);
                    cacc[1][4] = __fmaf_rn(zr.y, e1.x, cacc[1][4]);
                    cacc[1][5] = __fmaf_rn(zr.y, e1.y, cacc[1][5]);
                    cacc[1][6] = __fmaf_rn(zr.y, e1.z, cacc[1][6]);
                    cacc[1][7] = __fmaf_rn(zr.y, e1.w, cacc[1][7]);
                    cacc[2][0] = __fmaf_rn(zr.z, e0.x, cacc[2][0]);
                    cacc[2][1] = __fmaf_rn(zr.z, e0.y, cacc[2][1]);
                    cacc[2][2] = __fmaf_rn(zr.z, e0.z, cacc[2][2]);
                    cacc[2][3] = __fmaf_rn(zr.z, e0.w, cacc[2][3]);
                    cacc[2][4] = __fmaf_rn(zr.z, e1.x, cacc[2][4]);
                    cacc[2][5] = __fmaf_rn(zr.z, e1.y, cacc[2][5]);
                    cacc[2][6] = __fmaf_rn(zr.z, e1.z, cacc[2][6]);
                    cacc[2][7] = __fmaf_rn(zr.z, e1.w, cacc[2][7]);
                    cacc[3][0] = __fmaf_rn(zr.w, e0.x, cacc[3][0]);
                    cacc[3][1] = __fmaf_rn(zr.w, e0.y, cacc[3][1]);
                    cacc[3][2] = __fmaf_rn(zr.w, e0.z, cacc[3][2]);
                    cacc[3][3] = __fmaf_rn(zr.w, e0.w, cacc[3][3]);
                    cacc[3][4] = __fmaf_rn(zr.w, e1.x, cacc[3][4]);
                    cacc[3][5] = __fmaf_rn(zr.w, e1.y, cacc[3][5]);
                    cacc[3][6] = __fmaf_rn(zr.w, e1.z, cacc[3][6]);
                    cacc[3][7] = __fmaf_rn(zr.w, e1.w, cacc[3][7]);
                }
            }
        }

        // ---- FFMA epilogue: exact d, strict '<', ascending codes ----
        #pragma unroll
        for (int r = 0; r < 4; ++r) {
            float zq = zsq_s[i * 4 + r];
            #pragma unroll
            for (int c = 0; c < 8; ++c) {
                float d = __fmaf_rn(-2.0f, cacc[r][c], zq);
                if (d < bd[r]) { bd[r] = d; bi[r] = ct * 128 + j * 8 + c; }
            }
        }
        // ---- HMMA epilogue: per-(row, 8-code chunk) brackets ----
        #pragma unroll
        for (int nt = 0; nt < 8; ++nt) {
            float mA = fmaxf(facc[nt][0], facc[nt][1]);   // row rA
            float mB = fmaxf(facc[nt][2], facc[nt][3]);   // row rA+8
            mA = fmaxf(mA, __shfl_xor_sync(0xffffffffu, mA, 1));
            mA = fmaxf(mA, __shfl_xor_sync(0xffffffffu, mA, 2));
            mB = fmaxf(mB, __shfl_xor_sync(0xffffffffu, mB, 1));
            mB = fmaxf(mB, __shfl_xor_sync(0xffffffffu, mB, 2));
            if ((lane & 3) == 0) {
                int ch = 512 + ct * 16 + wn * 8 + nt;
                float dA = __fmaf_rn(mA, C2N, zsq_s[rA]);
                float dB = __fmaf_rn(mB, C2N, zsq_s[rA + 8]);
                size_t oA = (size_t)(row0 + rA) * 1024 + ch;
                size_t oB = (size_t)(row0 + rA + 8) * 1024 + ch;
                g_cminL[oA] = dA - EPS;  g_cminU[oA] = dA + EPS;
                g_cminL[oB] = dB - EPS;  g_cminU[oB] = dB + EPS;
            }
        }
    }

    // ---- cross-thread reduce of low-side exact best ----
    __syncthreads();
    #pragma unroll
    for (int r = 0; r < 4; ++r) {
        red_d[(i * 4 + r) * 16 + j] = bd[r];
        red_i[(i * 4 + r) * 16 + j] = bi[r];
    }
    __syncthreads();
    if (tid < 64) {
        float bdd = red_d[tid * 16];
        int   bii = red_i[tid * 16];
        #pragma unroll
        for (int jj = 1; jj < 16; ++jj) {
            float d  = red_d[tid * 16 + jj];
            int   ii = red_i[tid * 16 + jj];
            if (d < bdd || (d == bdd && ii < bii)) { bdd = d; bii = ii; }
        }
        g_lowd[row0 + tid] = bdd;
        g_lowi[row0 + tid] = bii;
    }
}

// ============================================================================
// Pass B: exact verify of high-side candidates + exact merge with low side
// ============================================================================
#define PB_SMEM (4 * 32 * 257 * 4 + 4 * 256 * 4 + 4 * 4 * 4)

__global__ __launch_bounds__(128) void vq_passb(
    const float* __restrict__ z,
    const float* __restrict__ emb,
    float* __restrict__ out_idx_f)
{
    extern __shared__ float smf[];
    const int w = threadIdx.x >> 5, lane = threadIdx.x & 31;
    float* esm = smf + w * (32 * 257);
    float* zsm = smf + 4 * (32 * 257) + w * 256;
    int*   slots = (int*)(smf + 4 * (32 * 257) + 4 * 256) + w * 4;
    const int r = blockIdx.x * 4 + w;
    const int b = r >> 10, hw = r & 1023;

    const float* cU = g_cminU + (size_t)r * 1024 + 512;
    const float* cL = g_cminL + (size_t)r * 1024 + 512;

    float mu = 3.4e38f;
    for (int g = 0; g < 16; ++g)
        mu = fminf(mu, cU[g * 32 + lane]);
    #pragma unroll
    for (int off = 16; off > 0; off >>= 1)
        mu = fminf(mu, __shfl_xor_sync(0xffffffffu, mu, off));
    const float thr = mu;

    for (int k = lane; k < 256; k += 32)
        zsm[k] = z[(size_t)b * 262144 + (size_t)k * 1024 + hw];
    __syncwarp();
    const float zsqv = g_zsq[r];

    float bdv = 3.4e38f;
    int   biv = 0x7fffffff;
    int   ns = 0;

    auto flush = [&](int n) {
        __syncwarp();
        for (int t = lane; t < n * 8 * 256; t += 32) {
            int rr = t >> 8, k = t & 255;
            int code = slots[rr >> 3] * 8 + (rr & 7);
            esm[rr * 257 + k] = emb[(size_t)code * 256 + k];
        }
        __syncwarp();
        if (lane < n * 8) {
            float dacc = 0.0f;
            const float* ep = esm + lane * 257;
            for (int k = 0; k < 256; ++k)
                dacc = __fmaf_rn(zsm[k], ep[k], dacc);
            float d = __fmaf_rn(-2.0f, dacc, zsqv);
            int idx = slots[lane >> 3] * 8 + (lane & 7);
            if (d < bdv || (d == bdv && idx < biv)) { bdv = d; biv = idx; }
        }
        __syncwarp();
    };

    for (int g = 0; g < 16; ++g) {
        float lv = cL[g * 32 + lane];
        unsigned m = __ballot_sync(0xffffffffu, lv <= thr);
        while (m) {
            int src = __ffs(m) - 1;
            m &= m - 1;
            if (lane == 0) slots[ns] = 512 + g * 32 + src;   // global chunk id
            ns++;
            if (ns == 4) { flush(4); ns = 0; }
        }
    }
    if (ns) flush(ns);

    #pragma unroll
    for (int off = 16; off > 0; off >>= 1) {
        float od = __shfl_down_sync(0xffffffffu, bdv, off);
        int   oi = __shfl_down_sync(0xffffffffu, biv, off);
        if (od < bdv || (od == bdv && oi < biv)) { bdv = od; biv = oi; }
    }
    if (lane == 0) {
        // merge with exact low side; low index < high index, so tie -> low
        float ld = g_lowd[r];
        int   li = g_lowi[r];
        if (ld < bdv || (ld == bdv && li < biv)) { bdv = ld; biv = li; }
        g_minidx[r]  = biv;
        out_idx_f[r] = (float)biv;
    }
}

// ============================================================================
// Output: straight-through z_q + loss (bit-identical to passing kernels)
// ============================================================================
__global__ __launch_bounds__(256) void vq_out_kernel(
    const float* __restrict__ z,
    const float* __restrict__ emb,
    float* __restrict__ out)
{
    const int o = blockIdx.x * 256 + threadIdx.x;
    const int c = (o >> 10) & 255;
    const int n = ((o >> 18) << 10) | (o & 1023);

    const int idx = g_minidx[n];
    const float zv = z[o];
    const float ev = __ldg(&emb[(size_t)idx * 256 + c]);
    const float diff = __fsub_rn(ev, zv);
    out[o] = __fadd_rn(zv, diff);
    const float sq = __fmul_rn(diff, diff);

    double v = (double)sq;
    #pragma unroll
    for (int off = 16; off > 0; off >>= 1)
        v += __shfl_down_sync(0xffffffffu, v, off);
    __shared__ double ws[8];
    if ((threadIdx.x & 31) == 0) ws[threadIdx.x >> 5] = v;
    __syncthreads();
    if (threadIdx.x == 0) {
        double s = 0.0;
        #pragma unroll
        for (int wv = 0; wv < 8; ++wv) s += ws[wv];
        atomicAdd(&g_loss_sum, s);
    }
}

__global__ void vq_finalize_kernel(float* __restrict__ out) {
    float m = (float)(g_loss_sum / (double)ZQ_SIZE);
    out[ZQ_SIZE] = __fadd_rn(__fmul_rn(BETA_F, m), m);
}

// ============================================================================
extern "C" void kernel_launch(void* const* d_in, const int* in_sizes, int n_in,
                              void* d_out, int out_size)
{
    const float* z   = (const float*)d_in[0];
    const float* emb = (const float*)d_in[1];
    float* out = (float*)d_out;

    cudaFuncSetAttribute(vq_hybrid,
                         cudaFuncAttributeMaxDynamicSharedMemorySize, HYB_SMEM);
    cudaFuncSetAttribute(vq_passb,
                         cudaFuncAttributeMaxDynamicSharedMemorySize, PB_SMEM);

    vq_init<<<1, 1>>>();
    vq_e16<<<NE * EDIM / 256, 256>>>(emb);
    vq_z16k<<<dim3(32, 8, 16), dim3(32, 8)>>>(z);
    vq_zsq<<<N_ROWS / 256, 256>>>(z);

    vq_hybrid<<<256, 256, HYB_SMEM>>>(z, emb);

    vq_passb<<<N_ROWS / 4, 128, PB_SMEM>>>(z, emb, out + ZQ_SIZE + 1);

    vq_out_kernel<<<ZQ_SIZE / 256, 256>>>(z, emb, out);
    vq_finalize_kernel<<<1, 1>>>(out);
}

// round 12
// speedup vs baseline: 8.2553x; 1.6246x over previous
#include <cuda_runtime.h>
#include <cuda_fp16.h>
#include <cstdint>

// ============================================================================
// VectorQuantizer — HMMA fp16 screen + exact fp32 verify (round-4 numerics,
// rel_err 0.0), re-gridded: persistent 152-CTA item loop -> ~96% SM balance
// (round-4 used 128 CTAs = 84% of GB300's 152 SMs).
//   screen: dot' = half(z) . half(e*2^14), fp32 accum; d = fmaf(dot',-2^-13,zsq)
//   |d_screen - d_exact| <= 7.4e-5; margin 4e-4. passB recomputes candidates
//   with the exact reference fp32 chain (ascending-k fmaf, first-index ties).
// ============================================================================

#define N_ROWS   16384
#define NE       8192
#define EDIM     256
#define ZQ_SIZE  4194304
#define BETA_F   1.0f
#define MARGIN_F 4.0e-4f
#define DSCALE   (-0.0001220703125f)   /* -2^-13 */

__device__ __align__(16) __half g_z16[N_ROWS * EDIM];   // [row][k]
__device__ __align__(16) __half g_e16[NE * EDIM];       // [code][k], * 2^14
__device__ __align__(16) float  g_cmin[N_ROWS * 256];   // per 32-code chunk
__device__ float  g_zsq[N_ROWS];
__device__ int    g_minidx[N_ROWS];
__device__ double g_loss_sum;

__device__ __forceinline__ uint32_t smem_u32(const void* p) {
    uint32_t a;
    asm("{ .reg .u64 t; cvta.to.shared.u64 t, %1; cvt.u32.u64 %0, t; }" : "=r"(a) : "l"(p));
    return a;
}
__device__ __forceinline__ void ldsm_x4(uint32_t r[4], uint32_t addr) {
    asm volatile("ldmatrix.sync.aligned.m8n8.x4.shared.b16 {%0,%1,%2,%3}, [%4];"
                 : "=r"(r[0]), "=r"(r[1]), "=r"(r[2]), "=r"(r[3]) : "r"(addr));
}
__device__ __forceinline__ void mma16816(float c[4], const uint32_t a[4], const uint32_t b[2]) {
    asm volatile("mma.sync.aligned.m16n8k16.row.col.f32.f16.f16.f32 "
                 "{%0,%1,%2,%3}, {%4,%5,%6,%7}, {%8,%9}, {%0,%1,%2,%3};"
                 : "+f"(c[0]), "+f"(c[1]), "+f"(c[2]), "+f"(c[3])
                 : "r"(a[0]), "r"(a[1]), "r"(a[2]), "r"(a[3]), "r"(b[0]), "r"(b[1]));
}

// ============================================================================
// Preprocessing (round-4 verbatim)
// ============================================================================
__global__ void vq_zero_kernel() { g_loss_sum = 0.0; }

__global__ __launch_bounds__(256) void vq_e16_kernel(const float* __restrict__ emb) {
    int i = blockIdx.x * 256 + threadIdx.x;
    g_e16[i] = __float2half_rn(emb[i] * 16384.0f);   // exact pow2 scale
}

__global__ __launch_bounds__(256) void vq_z16_kernel(const float* __restrict__ z) {
    __shared__ float t[32][33];
    const int b = blockIdx.z, k0 = blockIdx.y * 32, hw0 = blockIdx.x * 32;
    const int tx = threadIdx.x, ty = threadIdx.y;   // (32, 8)
    #pragma unroll
    for (int i = 0; i < 4; ++i) {
        int kl = ty + i * 8;
        t[kl][tx] = z[(size_t)b * 262144 + (size_t)(k0 + kl) * 1024 + hw0 + tx];
    }
    __syncthreads();
    #pragma unroll
    for (int i = 0; i < 4; ++i) {
        int hwl = ty + i * 8;
        g_z16[((size_t)b * 1024 + hw0 + hwl) * 256 + k0 + tx] = __float2half_rn(t[tx][hwl]);
    }
}

__global__ __launch_bounds__(256) void vq_zsq_kernel(const float* __restrict__ z) {
    const int n = blockIdx.x * 256 + threadIdx.x;
    const int b = n >> 10, hw = n & 1023;
    float s = 0.0f;
    for (int k = 0; k < 256; ++k) {
        float v = z[(size_t)b * 262144 + (size_t)k * 1024 + hw];
        s = __fadd_rn(s, __fmul_rn(v, v));
    }
    g_zsq[n] = s;
}

// ============================================================================
// Screen GEMM: persistent items. item = rt*8 + cs; rt = 128-row tile (0..127),
// cs = 1024-code slice (0..7). Grid 152, stride-152 item loop.
// smem: A [128 rows][264 halfs] @0 ; B [128 codes][264 halfs] @67584.
// ============================================================================
#define PITCH_B   528                   // bytes per row (264 halfs)
#define TILE_BYTES (128 * PITCH_B)      // 67584
#define GEMM_SMEM  (2 * TILE_BYTES)     // 135168
#define GRID_GEMM  152
#define N_ITEMS    1024

__global__ __launch_bounds__(256, 1) void vq_gemm_screen() {
    extern __shared__ char sm[];
    char* sA = sm;
    char* sB = sm + TILE_BYTES;
    const int tid  = threadIdx.x;
    const int warp = tid >> 5, lane = tid & 31;
    const int wm = warp & 3;          // 32 rows each
    const int wn = warp >> 2;         // 64 codes each
    const int q  = lane >> 2;

    const uint32_t aBase = smem_u32(sA)
        + (uint32_t)(wm * 32 + (lane & 15)) * PITCH_B + (uint32_t)(lane >> 4) * 16;
    const uint32_t bBase = smem_u32(sB)
        + (uint32_t)(wn * 64 + ((lane >> 4) << 3) + (lane & 7)) * PITCH_B
        + (uint32_t)((lane >> 3) & 1) * 16;

    int cur_rt = -1;
    float zsq4[4];

    for (int item = blockIdx.x; item < N_ITEMS; item += GRID_GEMM) {
        const int rt = item >> 3;          // row tile
        const int cs = item & 7;           // code slice (1024 codes)
        const int row0 = rt * 128;

        if (rt != cur_rt) {
            __syncthreads();   // prior mma done reading sA
            #pragma unroll
            for (int it = 0; it < 16; ++it) {
                int idx = it * 256 + tid;
                int r = idx >> 5, c = idx & 31;
                *(uint4*)(sA + r * PITCH_B + c * 16) =
                    *(const uint4*)(g_z16 + (size_t)(row0 + r) * 256 + c * 8);
            }
            cur_rt = rt;
            if ((lane & 3) == 0) {
                #pragma unroll
                for (int t = 0; t < 4; ++t)
                    zsq4[t] = g_zsq[row0 + wm * 32 + t * 8 + q];
            }
            // visibility of sA is ordered by the __syncthreads in the ct loop
        }

        for (int ct = 0; ct < 8; ++ct) {
            const int gct = cs * 8 + ct;   // global 128-code tile, 0..63
            __syncthreads();               // prior mma done reading sB (and orders sA)
            #pragma unroll
            for (int it = 0; it < 16; ++it) {
                int idx = it * 256 + tid;
                int r = idx >> 5, c = idx & 31;
                *(uint4*)(sB + r * PITCH_B + c * 16) =
                    *(const uint4*)(g_e16 + (size_t)(gct * 128 + r) * 256 + c * 8);
            }
            __syncthreads();

            float acc[2][8][4];
            #pragma unroll
            for (int mt = 0; mt < 2; ++mt)
                #pragma unroll
                for (int nt = 0; nt < 8; ++nt)
                    #pragma unroll
                    for (int i = 0; i < 4; ++i) acc[mt][nt][i] = 0.0f;

            #pragma unroll
            for (int ks = 0; ks < 16; ++ks) {
                uint32_t a[2][4];
                #pragma unroll
                for (int mt = 0; mt < 2; ++mt)
                    ldsm_x4(a[mt], aBase + (uint32_t)mt * (16 * PITCH_B) + (uint32_t)ks * 32);
                uint32_t b[8][2];
                #pragma unroll
                for (int np = 0; np < 4; ++np) {
                    uint32_t r4[4];
                    ldsm_x4(r4, bBase + (uint32_t)np * (16 * PITCH_B) + (uint32_t)ks * 32);
                    b[2 * np][0] = r4[0]; b[2 * np][1] = r4[1];
                    b[2 * np + 1][0] = r4[2]; b[2 * np + 1][1] = r4[3];
                }
                #pragma unroll
                for (int mt = 0; mt < 2; ++mt)
                    #pragma unroll
                    for (int nt = 0; nt < 8; ++nt)
                        mma16816(acc[mt][nt], a[mt], b[nt]);
            }

            // epilogue (round-4 verbatim): per-(row, 32-code chunk) min
            #pragma unroll
            for (int mt = 0; mt < 2; ++mt) {
                float mx[2][2];
                mx[0][0] = mx[0][1] = mx[1][0] = mx[1][1] = -3.4e38f;
                #pragma unroll
                for (int nt = 0; nt < 8; ++nt) {
                    const int ch = nt >> 2;
                    mx[0][ch] = fmaxf(mx[0][ch], fmaxf(acc[mt][nt][0], acc[mt][nt][1]));
                    mx[1][ch] = fmaxf(mx[1][ch], fmaxf(acc[mt][nt][2], acc[mt][nt][3]));
                }
                #pragma unroll
                for (int h = 0; h < 2; ++h)
                    #pragma unroll
                    for (int c = 0; c < 2; ++c) {
                        mx[h][c] = fmaxf(mx[h][c], __shfl_xor_sync(0xffffffffu, mx[h][c], 1));
                        mx[h][c] = fmaxf(mx[h][c], __shfl_xor_sync(0xffffffffu, mx[h][c], 2));
                    }
                if ((lane & 3) == 0) {
                    const int gc = gct * 4 + wn * 2;
                    #pragma unroll
                    for (int h = 0; h < 2; ++h) {
                        const int row = row0 + wm * 32 + mt * 16 + h * 8 + q;
                        const float zs = zsq4[mt * 2 + h];
                        g_cmin[(size_t)row * 256 + gc]     = __fmaf_rn(mx[h][0], DSCALE, zs);
                        g_cmin[(size_t)row * 256 + gc + 1] = __fmaf_rn(mx[h][1], DSCALE, zs);
                    }
                }
            }
        }
    }
}

// ============================================================================
// Pass B: exact fp32 verify (round-4 verbatim, rel_err 0.0)
// ============================================================================
#define PB_SMEM ((4 * 32 * 257 + 4 * 256) * 4)

__global__ __launch_bounds__(128) void vq_passb(
    const float* __restrict__ z,
    const float* __restrict__ emb,
    float* __restrict__ out_idx_f)
{
    extern __shared__ float smf[];
    const int w = threadIdx.x >> 5, lane = threadIdx.x & 31;
    float* esm = smf + w * (32 * 257);
    float* zsm = smf + 4 * (32 * 257) + w * 256;
    const int r = blockIdx.x * 4 + w;
    const int b = r >> 10, hw = r & 1023;

    float cv[8];
    const float* cp = g_cmin + (size_t)r * 256 + lane * 8;
    *(float4*)&cv[0] = *(const float4*)cp;
    *(float4*)&cv[4] = *(const float4*)(cp + 4);
    float rm = cv[0];
    #pragma unroll
    for (int i = 1; i < 8; ++i) rm = fminf(rm, cv[i]);
    #pragma unroll
    for (int off = 16; off > 0; off >>= 1)
        rm = fminf(rm, __shfl_xor_sync(0xffffffffu, rm, off));
    const float thr = rm + MARGIN_F;

    for (int k = lane; k < 256; k += 32)
        zsm[k] = z[(size_t)b * 262144 + (size_t)k * 1024 + hw];
    __syncwarp();
    const float zsqv = g_zsq[r];

    float bd = 3.4e38f;
    int   bi = 0x7fffffff;
    #pragma unroll
    for (int ci = 0; ci < 8; ++ci) {
        unsigned mask = __ballot_sync(0xffffffffu, cv[ci] <= thr);
        while (mask) {
            int l = __ffs(mask) - 1;
            mask &= mask - 1;
            int c = l * 8 + ci;               // candidate 32-code chunk
            for (int t = lane; t < 32 * 256; t += 32) {
                int rr = t >> 8, k = t & 255;
                esm[rr * 257 + k] = emb[(size_t)(c * 32 + rr) * 256 + k];
            }
            __syncwarp();
            float dacc = 0.0f;
            const float* ep = esm + lane * 257;
            for (int k = 0; k < 256; ++k)
                dacc = __fmaf_rn(zsm[k], ep[k], dacc);
            float d = __fmaf_rn(-2.0f, dacc, zsqv);
            int idx = c * 32 + lane;
            if (d < bd || (d == bd && idx < bi)) { bd = d; bi = idx; }
            __syncwarp();
        }
    }
    #pragma unroll
    for (int off = 16; off > 0; off >>= 1) {
        float od = __shfl_down_sync(0xffffffffu, bd, off);
        int   oi = __shfl_down_sync(0xffffffffu, bi, off);
        if (od < bd || (od == bd && oi < bi)) { bd = od; bi = oi; }
    }
    if (lane == 0) {
        g_minidx[r]  = bi;
        out_idx_f[r] = (float)bi;
    }
}

// ============================================================================
// Output: straight-through z_q + loss (validated verbatim)
// ============================================================================
__global__ __launch_bounds__(256) void vq_out_kernel(
    const float* __restrict__ z,
    const float* __restrict__ emb,
    float* __restrict__ out)
{
    const int o = blockIdx.x * 256 + threadIdx.x;
    const int c = (o >> 10) & 255;
    const int n = ((o >> 18) << 10) | (o & 1023);

    const int idx = g_minidx[n];
    const float zv = z[o];
    const float ev = __ldg(&emb[(size_t)idx * 256 + c]);
    const float diff = __fsub_rn(ev, zv);
    out[o] = __fadd_rn(zv, diff);
    const float sq = __fmul_rn(diff, diff);

    double v = (double)sq;
    #pragma unroll
    for (int off = 16; off > 0; off >>= 1)
        v += __shfl_down_sync(0xffffffffu, v, off);
    __shared__ double ws[8];
    if ((threadIdx.x & 31) == 0) ws[threadIdx.x >> 5] = v;
    __syncthreads();
    if (threadIdx.x == 0) {
        double s = 0.0;
        #pragma unroll
        for (int wv = 0; wv < 8; ++wv) s += ws[wv];
        atomicAdd(&g_loss_sum, s);
    }
}

__global__ void vq_finalize_kernel(float* __restrict__ out) {
    float m = (float)(g_loss_sum / (double)ZQ_SIZE);
    out[ZQ_SIZE] = __fadd_rn(__fmul_rn(BETA_F, m), m);
}

// ============================================================================
extern "C" void kernel_launch(void* const* d_in, const int* in_sizes, int n_in,
                              void* d_out, int out_size)
{
    const float* z   = (const float*)d_in[0];
    const float* emb = (const float*)d_in[1];
    float* out = (float*)d_out;

    cudaFuncSetAttribute(vq_gemm_screen,
                         cudaFuncAttributeMaxDynamicSharedMemorySize, GEMM_SMEM);
    cudaFuncSetAttribute(vq_passb,
                         cudaFuncAttributeMaxDynamicSharedMemorySize, PB_SMEM);

    vq_zero_kernel<<<1, 1>>>();
    vq_e16_kernel<<<NE * EDIM / 256, 256>>>(emb);
    vq_z16_kernel<<<dim3(32, 8, 16), dim3(32, 8)>>>(z);
    vq_zsq_kernel<<<N_ROWS / 256, 256>>>(z);

    vq_gemm_screen<<<GRID_GEMM, 256, GEMM_SMEM>>>();

    vq_passb<<<N_ROWS / 4, 128, PB_SMEM>>>(z, emb, out + ZQ_SIZE + 1);

    vq_out_kernel<<<ZQ_SIZE / 256, 256>>>(z, emb, out);
    vq_finalize_kernel<<<1, 1>>>(out);
}

// round 13
// speedup vs baseline: 9.4621x; 1.1462x over previous
#include <cuda_runtime.h>
#include <cuda_fp16.h>
#include <cstdint>

// ============================================================================
// VectorQuantizer — HMMA fp16 screen (persistent 152-CTA grid, validated
// round-12) + exact fp32 verify. Round-13 delta: screen stores per-8-code
// chunk mins (4x finer than round-12's 32-code chunks) so passB verifies
// ~4x fewer codes; passB uses the slots/flush machinery validated in
// rounds 7/8/10 (rel_err 0.0 each time).
//   screen: dot' = half(z).half(e*2^14), fp32 accum; d = fmaf(dot',-2^-13,zsq)
//   |d_screen - d_exact| <= 7.4e-5; margin 4e-4 (5x slack).
// ============================================================================

#define N_ROWS   16384
#define NE       8192
#define EDIM     256
#define ZQ_SIZE  4194304
#define BETA_F   1.0f
#define MARGIN_F 4.0e-4f
#define DSCALE   (-0.0001220703125f)   /* -2^-13 */

__device__ __align__(16) __half g_z16[N_ROWS * EDIM];   // [row][k]
__device__ __align__(16) __half g_e16[NE * EDIM];       // [code][k], * 2^14
__device__ __align__(16) float  g_cmin[N_ROWS * 1024];  // per 8-code chunk
__device__ float  g_zsq[N_ROWS];
__device__ int    g_minidx[N_ROWS];
__device__ double g_loss_sum;

__device__ __forceinline__ uint32_t smem_u32(const void* p) {
    uint32_t a;
    asm("{ .reg .u64 t; cvta.to.shared.u64 t, %1; cvt.u32.u64 %0, t; }" : "=r"(a) : "l"(p));
    return a;
}
__device__ __forceinline__ void ldsm_x4(uint32_t r[4], uint32_t addr) {
    asm volatile("ldmatrix.sync.aligned.m8n8.x4.shared.b16 {%0,%1,%2,%3}, [%4];"
                 : "=r"(r[0]), "=r"(r[1]), "=r"(r[2]), "=r"(r[3]) : "r"(addr));
}
__device__ __forceinline__ void mma16816(float c[4], const uint32_t a[4], const uint32_t b[2]) {
    asm volatile("mma.sync.aligned.m16n8k16.row.col.f32.f16.f16.f32 "
                 "{%0,%1,%2,%3}, {%4,%5,%6,%7}, {%8,%9}, {%0,%1,%2,%3};"
                 : "+f"(c[0]), "+f"(c[1]), "+f"(c[2]), "+f"(c[3])
                 : "r"(a[0]), "r"(a[1]), "r"(a[2]), "r"(a[3]), "r"(b[0]), "r"(b[1]));
}

// ============================================================================
// Preprocessing (validated)
// ============================================================================
__global__ __launch_bounds__(256) void vq_e16_kernel(const float* __restrict__ emb) {
    int i = blockIdx.x * 256 + threadIdx.x;
    g_e16[i] = __float2half_rn(emb[i] * 16384.0f);   // exact pow2 scale
    if (blockIdx.x == 0 && threadIdx.x == 0) g_loss_sum = 0.0;
}

__global__ __launch_bounds__(256) void vq_z16_kernel(const float* __restrict__ z) {
    __shared__ float t[32][33];
    const int b = blockIdx.z, k0 = blockIdx.y * 32, hw0 = blockIdx.x * 32;
    const int tx = threadIdx.x, ty = threadIdx.y;   // (32, 8)
    #pragma unroll
    for (int i = 0; i < 4; ++i) {
        int kl = ty + i * 8;
        t[kl][tx] = z[(size_t)b * 262144 + (size_t)(k0 + kl) * 1024 + hw0 + tx];
    }
    __syncthreads();
    #pragma unroll
    for (int i = 0; i < 4; ++i) {
        int hwl = ty + i * 8;
        g_z16[((size_t)b * 1024 + hw0 + hwl) * 256 + k0 + tx] = __float2half_rn(t[tx][hwl]);
    }
}

__global__ __launch_bounds__(256) void vq_zsq_kernel(const float* __restrict__ z) {
    const int n = blockIdx.x * 256 + threadIdx.x;
    const int b = n >> 10, hw = n & 1023;
    float s = 0.0f;
    for (int k = 0; k < 256; ++k) {
        float v = z[(size_t)b * 262144 + (size_t)k * 1024 + hw];
        s = __fadd_rn(s, __fmul_rn(v, v));
    }
    g_zsq[n] = s;
}

// ============================================================================
// Screen GEMM: persistent items (round-12 verbatim except 8-code epilogue).
// item = rt*8 + cs; rt = 128-row tile, cs = 1024-code slice. Grid 152.
// ============================================================================
#define PITCH_B   528
#define TILE_BYTES (128 * PITCH_B)      // 67584
#define GEMM_SMEM  (2 * TILE_BYTES)     // 135168
#define GRID_GEMM  152
#define N_ITEMS    1024

__global__ __launch_bounds__(256, 1) void vq_gemm_screen() {
    extern __shared__ char sm[];
    char* sA = sm;
    char* sB = sm + TILE_BYTES;
    const int tid  = threadIdx.x;
    const int warp = tid >> 5, lane = tid & 31;
    const int wm = warp & 3;          // 32 rows each
    const int wn = warp >> 2;         // 64 codes each
    const int q  = lane >> 2;

    const uint32_t aBase = smem_u32(sA)
        + (uint32_t)(wm * 32 + (lane & 15)) * PITCH_B + (uint32_t)(lane >> 4) * 16;
    const uint32_t bBase = smem_u32(sB)
        + (uint32_t)(wn * 64 + ((lane >> 4) << 3) + (lane & 7)) * PITCH_B
        + (uint32_t)((lane >> 3) & 1) * 16;

    int cur_rt = -1;
    float zsq4[4];

    for (int item = blockIdx.x; item < N_ITEMS; item += GRID_GEMM) {
        const int rt = item >> 3;
        const int cs = item & 7;
        const int row0 = rt * 128;

        if (rt != cur_rt) {
            __syncthreads();
            #pragma unroll
            for (int it = 0; it < 16; ++it) {
                int idx = it * 256 + tid;
                int r = idx >> 5, c = idx & 31;
                *(uint4*)(sA + r * PITCH_B + c * 16) =
                    *(const uint4*)(g_z16 + (size_t)(row0 + r) * 256 + c * 8);
            }
            cur_rt = rt;
            if ((lane & 3) == 0) {
                #pragma unroll
                for (int t = 0; t < 4; ++t)
                    zsq4[t] = g_zsq[row0 + wm * 32 + t * 8 + q];
            }
        }

        for (int ct = 0; ct < 8; ++ct) {
            const int gct = cs * 8 + ct;   // global 128-code tile, 0..63
            __syncthreads();
            #pragma unroll
            for (int it = 0; it < 16; ++it) {
                int idx = it * 256 + tid;
                int r = idx >> 5, c = idx & 31;
                *(uint4*)(sB + r * PITCH_B + c * 16) =
                    *(const uint4*)(g_e16 + (size_t)(gct * 128 + r) * 256 + c * 8);
            }
            __syncthreads();

            float acc[2][8][4];
            #pragma unroll
            for (int mt = 0; mt < 2; ++mt)
                #pragma unroll
                for (int nt = 0; nt < 8; ++nt)
                    #pragma unroll
                    for (int i = 0; i < 4; ++i) acc[mt][nt][i] = 0.0f;

            #pragma unroll
            for (int ks = 0; ks < 16; ++ks) {
                uint32_t a[2][4];
                #pragma unroll
                for (int mt = 0; mt < 2; ++mt)
                    ldsm_x4(a[mt], aBase + (uint32_t)mt * (16 * PITCH_B) + (uint32_t)ks * 32);
                uint32_t b[8][2];
                #pragma unroll
                for (int np = 0; np < 4; ++np) {
                    uint32_t r4[4];
                    ldsm_x4(r4, bBase + (uint32_t)np * (16 * PITCH_B) + (uint32_t)ks * 32);
                    b[2 * np][0] = r4[0]; b[2 * np][1] = r4[1];
                    b[2 * np + 1][0] = r4[2]; b[2 * np + 1][1] = r4[3];
                }
                #pragma unroll
                for (int mt = 0; mt < 2; ++mt)
                    #pragma unroll
                    for (int nt = 0; nt < 8; ++nt)
                        mma16816(acc[mt][nt], a[mt], b[nt]);
            }

            // epilogue: per-(row, 8-code chunk) min (shuffle map = round-4's,
            // minus the 4-nt merge). chunk id = gct*16 + wn*8 + nt.
            #pragma unroll
            for (int mt = 0; mt < 2; ++mt) {
                #pragma unroll
                for (int nt = 0; nt < 8; ++nt) {
                    float mA = fmaxf(acc[mt][nt][0], acc[mt][nt][1]);  // row .. + q
                    float mB = fmaxf(acc[mt][nt][2], acc[mt][nt][3]);  // row .. + q + 8
                    mA = fmaxf(mA, __shfl_xor_sync(0xffffffffu, mA, 1));
                    mA = fmaxf(mA, __shfl_xor_sync(0xffffffffu, mA, 2));
                    mB = fmaxf(mB, __shfl_xor_sync(0xffffffffu, mB, 1));
                    mB = fmaxf(mB, __shfl_xor_sync(0xffffffffu, mB, 2));
                    if ((lane & 3) == 0) {
                        const int ch = gct * 16 + wn * 8 + nt;
                        const int rowA = row0 + wm * 32 + mt * 16 + q;
                        g_cmin[(size_t)rowA * 1024 + ch] =
                            __fmaf_rn(mA, DSCALE, zsq4[mt * 2]);
                        g_cmin[(size_t)(rowA + 8) * 1024 + ch] =
                            __fmaf_rn(mB, DSCALE, zsq4[mt * 2 + 1]);
                    }
                }
            }
        }
    }
}

// ============================================================================
// Pass B: exact fp32 verify over 8-code candidate chunks (slots/flush
// machinery validated rel_err 0.0 in rounds 7/8/10). Block = 4 warps = 4 rows.
// ============================================================================
#define PB_SMEM (4 * 32 * 257 * 4 + 4 * 256 * 4 + 4 * 4 * 4)

__global__ __launch_bounds__(128) void vq_passb(
    const float* __restrict__ z,
    const float* __restrict__ emb,
    float* __restrict__ out_idx_f)
{
    extern __shared__ float smf[];
    const int w = threadIdx.x >> 5, lane = threadIdx.x & 31;
    float* esm = smf + w * (32 * 257);
    float* zsm = smf + 4 * (32 * 257) + w * 256;
    int*   slots = (int*)(smf + 4 * (32 * 257) + 4 * 256) + w * 4;
    const int r = blockIdx.x * 4 + w;
    const int b = r >> 10, hw = r & 1023;

    const float* cm = g_cmin + (size_t)r * 1024;

    // load 32 chunk-mins per lane, compute row min
    float cv[32];
    #pragma unroll
    for (int g = 0; g < 8; ++g) {
        float4 v = *(const float4*)(cm + g * 128 + lane * 4);
        cv[g * 4 + 0] = v.x; cv[g * 4 + 1] = v.y;
        cv[g * 4 + 2] = v.z; cv[g * 4 + 3] = v.w;
    }
    float rm = cv[0];
    #pragma unroll
    for (int i = 1; i < 32; ++i) rm = fminf(rm, cv[i]);
    #pragma unroll
    for (int off = 16; off > 0; off >>= 1)
        rm = fminf(rm, __shfl_xor_sync(0xffffffffu, rm, off));
    const float thr = rm + MARGIN_F;

    for (int k = lane; k < 256; k += 32)
        zsm[k] = z[(size_t)b * 262144 + (size_t)k * 1024 + hw];
    __syncwarp();
    const float zsqv = g_zsq[r];

    float bd = 3.4e38f;
    int   bi = 0x7fffffff;
    int   ns = 0;

    auto flush = [&](int n) {
        __syncwarp();
        for (int t = lane; t < n * 8 * 256; t += 32) {
            int rr = t >> 8, k = t & 255;
            int code = slots[rr >> 3] * 8 + (rr & 7);
            esm[rr * 257 + k] = emb[(size_t)code * 256 + k];
        }
        __syncwarp();
        if (lane < n * 8) {
            float dacc = 0.0f;
            const float* ep = esm + lane * 257;
            for (int k = 0; k < 256; ++k)
                dacc = __fmaf_rn(zsm[k], ep[k], dacc);
            float d = __fmaf_rn(-2.0f, dacc, zsqv);
            int idx = slots[lane >> 3] * 8 + (lane & 7);
            if (d < bd || (d == bd && idx < bi)) { bd = d; bi = idx; }
        }
        __syncwarp();
    };

    // candidates in ascending chunk order: lane-major within group g
    #pragma unroll
    for (int g = 0; g < 8; ++g) {
        #pragma unroll
        for (int s = 0; s < 4; ++s) {
            // chunk id = g*128 + lane*4 + s; ascending in (g, lane, s)?  No:
            // must process in ascending chunk id for first-index ties.
            // chunk = g*128 + lane*4 + s -> within fixed g, ascending lane.
            // ballot scan handles lane order; s inner ascending per lane.
            unsigned m = __ballot_sync(0xffffffffu, cv[g * 4 + s] <= thr);
            while (m) {
                int src = __ffs(m) - 1;
                m &= m - 1;
                if (lane == 0) slots[ns] = g * 128 + src * 4 + s;
                ns++;
                if (ns == 4) { flush(4); ns = 0; }
            }
        }
    }
    if (ns) flush(ns);

    #pragma unroll
    for (int off = 16; off > 0; off >>= 1) {
        float od = __shfl_down_sync(0xffffffffu, bd, off);
        int   oi = __shfl_down_sync(0xffffffffu, bi, off);
        if (od < bd || (od == bd && oi < bi)) { bd = od; bi = oi; }
    }
    if (lane == 0) {
        g_minidx[r]  = bi;
        out_idx_f[r] = (float)bi;
    }
}

// ============================================================================
// Output: straight-through z_q + loss (validated verbatim)
// ============================================================================
__global__ __launch_bounds__(256) void vq_out_kernel(
    const float* __restrict__ z,
    const float* __restrict__ emb,
    float* __restrict__ out)
{
    const int o = blockIdx.x * 256 + threadIdx.x;
    const int c = (o >> 10) & 255;
    const int n = ((o >> 18) << 10) | (o & 1023);

    const int idx = g_minidx[n];
    const float zv = z[o];
    const float ev = __ldg(&emb[(size_t)idx * 256 + c]);
    const float diff = __fsub_rn(ev, zv);
    out[o] = __fadd_rn(zv, diff);
    const float sq = __fmul_rn(diff, diff);

    double v = (double)sq;
    #pragma unroll
    for (int off = 16; off > 0; off >>= 1)
        v += __shfl_down_sync(0xffffffffu, v, off);
    __shared__ double ws[8];
    if ((threadIdx.x & 31) == 0) ws[threadIdx.x >> 5] = v;
    __syncthreads();
    if (threadIdx.x == 0) {
        double s = 0.0;
        #pragma unroll
        for (int wv = 0; wv < 8; ++wv) s += ws[wv];
        atomicAdd(&g_loss_sum, s);
    }
}

__global__ void vq_finalize_kernel(float* __restrict__ out) {
    float m = (float)(g_loss_sum / (double)ZQ_SIZE);
    out[ZQ_SIZE] = __fadd_rn(__fmul_rn(BETA_F, m), m);
}

// ============================================================================
extern "C" void kernel_launch(void* const* d_in, const int* in_sizes, int n_in,
                              void* d_out, int out_size)
{
    const float* z   = (const float*)d_in[0];
    const float* emb = (const float*)d_in[1];
    float* out = (float*)d_out;

    cudaFuncSetAttribute(vq_gemm_screen,
                         cudaFuncAttributeMaxDynamicSharedMemorySize, GEMM_SMEM);
    cudaFuncSetAttribute(vq_passb,
                         cudaFuncAttributeMaxDynamicSharedMemorySize, PB_SMEM);

    vq_e16_kernel<<<NE * EDIM / 256, 256>>>(emb);
    vq_z16_kernel<<<dim3(32, 8, 16), dim3(32, 8)>>>(z);
    vq_zsq_kernel<<<N_ROWS / 256, 256>>>(z);

    vq_gemm_screen<<<GRID_GEMM, 256, GEMM_SMEM>>>();

    vq_passb<<<N_ROWS / 4, 128, PB_SMEM>>>(z, emb, out + ZQ_SIZE + 1);

    vq_out_kernel<<<ZQ_SIZE / 256, 256>>>(z, emb, out);
    vq_finalize_kernel<<<1, 1>>>(out);
}

// round 15
// speedup vs baseline: 27.0336x; 2.8570x over previous
#include <cuda_runtime.h>
#include <cuda_fp16.h>
#include <cstdint>

// ============================================================================
// VectorQuantizer — HMMA fp16 screen (round-13 verbatim) + exact fp32 verify.
// Round-14 delta: passB rewritten for occupancy — no 131KB esm staging
// (1 block/SM pathology); candidate dots read emb directly from L2.
// smem 8.3KB, 8 rows/block, 2048 blocks. Numerics unchanged (rel_err 0.0).
// ============================================================================

#define N_ROWS   16384
#define NE       8192
#define EDIM     256
#define ZQ_SIZE  4194304
#define BETA_F   1.0f
#define MARGIN_F 4.0e-4f
#define DSCALE   (-0.0001220703125f)   /* -2^-13 */

__device__ __align__(16) __half g_z16[N_ROWS * EDIM];   // [row][k]
__device__ __align__(16) __half g_e16[NE * EDIM];       // [code][k], * 2^14
__device__ __align__(16) float  g_cmin[N_ROWS * 1024];  // per 8-code chunk
__device__ float  g_zsq[N_ROWS];
__device__ int    g_minidx[N_ROWS];
__device__ double g_loss_sum;

__device__ __forceinline__ uint32_t smem_u32(const void* p) {
    uint32_t a;
    asm("{ .reg .u64 t; cvta.to.shared.u64 t, %1; cvt.u32.u64 %0, t; }" : "=r"(a) : "l"(p));
    return a;
}
__device__ __forceinline__ void ldsm_x4(uint32_t r[4], uint32_t addr) {
    asm volatile("ldmatrix.sync.aligned.m8n8.x4.shared.b16 {%0,%1,%2,%3}, [%4];"
                 : "=r"(r[0]), "=r"(r[1]), "=r"(r[2]), "=r"(r[3]) : "r"(addr));
}
__device__ __forceinline__ void mma16816(float c[4], const uint32_t a[4], const uint32_t b[2]) {
    asm volatile("mma.sync.aligned.m16n8k16.row.col.f32.f16.f16.f32 "
                 "{%0,%1,%2,%3}, {%4,%5,%6,%7}, {%8,%9}, {%0,%1,%2,%3};"
                 : "+f"(c[0]), "+f"(c[1]), "+f"(c[2]), "+f"(c[3])
                 : "r"(a[0]), "r"(a[1]), "r"(a[2]), "r"(a[3]), "r"(b[0]), "r"(b[1]));
}

// ============================================================================
// Preprocessing (round-13 verbatim)
// ============================================================================
__global__ __launch_bounds__(256) void vq_e16_kernel(const float* __restrict__ emb) {
    int i = blockIdx.x * 256 + threadIdx.x;
    g_e16[i] = __float2half_rn(emb[i] * 16384.0f);   // exact pow2 scale
    if (blockIdx.x == 0 && threadIdx.x == 0) g_loss_sum = 0.0;
}

__global__ __launch_bounds__(256) void vq_z16_kernel(const float* __restrict__ z) {
    __shared__ float t[32][33];
    const int b = blockIdx.z, k0 = blockIdx.y * 32, hw0 = blockIdx.x * 32;
    const int tx = threadIdx.x, ty = threadIdx.y;   // (32, 8)
    #pragma unroll
    for (int i = 0; i < 4; ++i) {
        int kl = ty + i * 8;
        t[kl][tx] = z[(size_t)b * 262144 + (size_t)(k0 + kl) * 1024 + hw0 + tx];
    }
    __syncthreads();
    #pragma unroll
    for (int i = 0; i < 4; ++i) {
        int hwl = ty + i * 8;
        g_z16[((size_t)b * 1024 + hw0 + hwl) * 256 + k0 + tx] = __float2half_rn(t[tx][hwl]);
    }
}

__global__ __launch_bounds__(256) void vq_zsq_kernel(const float* __restrict__ z) {
    const int n = blockIdx.x * 256 + threadIdx.x;
    const int b = n >> 10, hw = n & 1023;
    float s = 0.0f;
    for (int k = 0; k < 256; ++k) {
        float v = z[(size_t)b * 262144 + (size_t)k * 1024 + hw];
        s = __fadd_rn(s, __fmul_rn(v, v));
    }
    g_zsq[n] = s;
}

// ============================================================================
// Screen GEMM (round-13 verbatim — the control variable this round)
// ============================================================================
#define PITCH_B   528
#define TILE_BYTES (128 * PITCH_B)      // 67584
#define GEMM_SMEM  (2 * TILE_BYTES)     // 135168
#define GRID_GEMM  152
#define N_ITEMS    1024

__global__ __launch_bounds__(256, 1) void vq_gemm_screen() {
    extern __shared__ char sm[];
    char* sA = sm;
    char* sB = sm + TILE_BYTES;
    const int tid  = threadIdx.x;
    const int warp = tid >> 5, lane = tid & 31;
    const int wm = warp & 3;
    const int wn = warp >> 2;
    const int q  = lane >> 2;

    const uint32_t aBase = smem_u32(sA)
        + (uint32_t)(wm * 32 + (lane & 15)) * PITCH_B + (uint32_t)(lane >> 4) * 16;
    const uint32_t bBase = smem_u32(sB)
        + (uint32_t)(wn * 64 + ((lane >> 4) << 3) + (lane & 7)) * PITCH_B
        + (uint32_t)((lane >> 3) & 1) * 16;

    int cur_rt = -1;
    float zsq4[4];

    for (int item = blockIdx.x; item < N_ITEMS; item += GRID_GEMM) {
        const int rt = item >> 3;
        const int cs = item & 7;
        const int row0 = rt * 128;

        if (rt != cur_rt) {
            __syncthreads();
            #pragma unroll
            for (int it = 0; it < 16; ++it) {
                int idx = it * 256 + tid;
                int r = idx >> 5, c = idx & 31;
                *(uint4*)(sA + r * PITCH_B + c * 16) =
                    *(const uint4*)(g_z16 + (size_t)(row0 + r) * 256 + c * 8);
            }
            cur_rt = rt;
            if ((lane & 3) == 0) {
                #pragma unroll
                for (int t = 0; t < 4; ++t)
                    zsq4[t] = g_zsq[row0 + wm * 32 + t * 8 + q];
            }
        }

        for (int ct = 0; ct < 8; ++ct) {
            const int gct = cs * 8 + ct;
            __syncthreads();
            #pragma unroll
            for (int it = 0; it < 16; ++it) {
                int idx = it * 256 + tid;
                int r = idx >> 5, c = idx & 31;
                *(uint4*)(sB + r * PITCH_B + c * 16) =
                    *(const uint4*)(g_e16 + (size_t)(gct * 128 + r) * 256 + c * 8);
            }
            __syncthreads();

            float acc[2][8][4];
            #pragma unroll
            for (int mt = 0; mt < 2; ++mt)
                #pragma unroll
                for (int nt = 0; nt < 8; ++nt)
                    #pragma unroll
                    for (int i = 0; i < 4; ++i) acc[mt][nt][i] = 0.0f;

            #pragma unroll
            for (int ks = 0; ks < 16; ++ks) {
                uint32_t a[2][4];
                #pragma unroll
                for (int mt = 0; mt < 2; ++mt)
                    ldsm_x4(a[mt], aBase + (uint32_t)mt * (16 * PITCH_B) + (uint32_t)ks * 32);
                uint32_t b[8][2];
                #pragma unroll
                for (int np = 0; np < 4; ++np) {
                    uint32_t r4[4];
                    ldsm_x4(r4, bBase + (uint32_t)np * (16 * PITCH_B) + (uint32_t)ks * 32);
                    b[2 * np][0] = r4[0]; b[2 * np][1] = r4[1];
                    b[2 * np + 1][0] = r4[2]; b[2 * np + 1][1] = r4[3];
                }
                #pragma unroll
                for (int mt = 0; mt < 2; ++mt)
                    #pragma unroll
                    for (int nt = 0; nt < 8; ++nt)
                        mma16816(acc[mt][nt], a[mt], b[nt]);
            }

            #pragma unroll
            for (int mt = 0; mt < 2; ++mt) {
                #pragma unroll
                for (int nt = 0; nt < 8; ++nt) {
                    float mA = fmaxf(acc[mt][nt][0], acc[mt][nt][1]);
                    float mB = fmaxf(acc[mt][nt][2], acc[mt][nt][3]);
                    mA = fmaxf(mA, __shfl_xor_sync(0xffffffffu, mA, 1));
                    mA = fmaxf(mA, __shfl_xor_sync(0xffffffffu, mA, 2));
                    mB = fmaxf(mB, __shfl_xor_sync(0xffffffffu, mB, 1));
                    mB = fmaxf(mB, __shfl_xor_sync(0xffffffffu, mB, 2));
                    if ((lane & 3) == 0) {
                        const int ch = gct * 16 + wn * 8 + nt;
                        const int rowA = row0 + wm * 32 + mt * 16 + q;
                        g_cmin[(size_t)rowA * 1024 + ch] =
                            __fmaf_rn(mA, DSCALE, zsq4[mt * 2]);
                        g_cmin[(size_t)(rowA + 8) * 1024 + ch] =
                            __fmaf_rn(mB, DSCALE, zsq4[mt * 2 + 1]);
                    }
                }
            }
        }
    }
}

// ============================================================================
// Pass B (REWRITTEN): high-occupancy exact fp32 verify.
// 256 threads = 8 warps = 8 rows/block; smem = zsm 8x256 f32 + slots 8x4 int
// (8.3 KB -> ~8 blocks/SM vs round-13's 132 KB -> 1 block/SM).
// Candidate dots read emb directly (L2-resident); exact chain + idx tie-break
// identical to all prior rel_err-0 rounds (order-independent via tie-break).
// ============================================================================
#define PB_SMEM (8 * 256 * 4 + 8 * 4 * 4)

__global__ __launch_bounds__(256) void vq_passb(
    const float* __restrict__ z,
    const float* __restrict__ emb,
    float* __restrict__ out_idx_f)
{
    extern __shared__ float smf[];
    const int w = threadIdx.x >> 5, lane = threadIdx.x & 31;
    float* zsm = smf + w * 256;
    int*   slots = (int*)(smf + 8 * 256) + w * 4;
    const int r = blockIdx.x * 8 + w;
    const int b = r >> 10, hw = r & 1023;

    const float* cm = g_cmin + (size_t)r * 1024;

    // 32 chunk-mins per lane; row min via butterfly
    float cv[32];
    #pragma unroll
    for (int g = 0; g < 8; ++g) {
        float4 v = *(const float4*)(cm + g * 128 + lane * 4);
        cv[g * 4 + 0] = v.x; cv[g * 4 + 1] = v.y;
        cv[g * 4 + 2] = v.z; cv[g * 4 + 3] = v.w;
    }
    float rm = cv[0];
    #pragma unroll
    for (int i = 1; i < 32; ++i) rm = fminf(rm, cv[i]);
    #pragma unroll
    for (int off = 16; off > 0; off >>= 1)
        rm = fminf(rm, __shfl_xor_sync(0xffffffffu, rm, off));
    const float thr = rm + MARGIN_F;

    // stage z row (MLP-8 unrolled strided loads)
    #pragma unroll
    for (int kk = 0; kk < 8; ++kk)
        zsm[kk * 32 + lane] = z[(size_t)b * 262144 + (size_t)(kk * 32 + lane) * 1024 + hw];
    __syncwarp();
    const float zsqv = g_zsq[r];

    float bd = 3.4e38f;
    int   bi = 0x7fffffff;
    int   ns = 0;

    auto flush = [&](int n) {
        __syncwarp();
        if (lane < n * 8) {
            const int code = slots[lane >> 3] * 8 + (lane & 7);
            const float* ep = emb + (size_t)code * 256;
            float dacc = 0.0f;
            #pragma unroll 8
            for (int k = 0; k < 256; ++k)
                dacc = __fmaf_rn(zsm[k], __ldg(ep + k), dacc);
            float d = __fmaf_rn(-2.0f, dacc, zsqv);
            if (d < bd || (d == bd && code < bi)) { bd = d; bi = code; }
        }
        __syncwarp();
    };

    #pragma unroll
    for (int g = 0; g < 8; ++g) {
        #pragma unroll
        for (int s = 0; s < 4; ++s) {
            unsigned m = __ballot_sync(0xffffffffu, cv[g * 4 + s] <= thr);
            while (m) {
                int src = __ffs(m) - 1;
                m &= m - 1;
                if (lane == 0) slots[ns] = g * 128 + src * 4 + s;
                ns++;
                if (ns == 4) { flush(4); ns = 0; }
            }
        }
    }
    if (ns) flush(ns);

    #pragma unroll
    for (int off = 16; off > 0; off >>= 1) {
        float od = __shfl_down_sync(0xffffffffu, bd, off);
        int   oi = __shfl_down_sync(0xffffffffu, bi, off);
        if (od < bd || (od == bd && oi < bi)) { bd = od; bi = oi; }
    }
    if (lane == 0) {
        g_minidx[r]  = bi;
        out_idx_f[r] = (float)bi;
    }
}

// ============================================================================
// Output: straight-through z_q + loss (validated verbatim)
// ============================================================================
__global__ __launch_bounds__(256) void vq_out_kernel(
    const float* __restrict__ z,
    const float* __restrict__ emb,
    float* __restrict__ out)
{
    const int o = blockIdx.x * 256 + threadIdx.x;
    const int c = (o >> 10) & 255;
    const int n = ((o >> 18) << 10) | (o & 1023);

    const int idx = g_minidx[n];
    const float zv = z[o];
    const float ev = __ldg(&emb[(size_t)idx * 256 + c]);
    const float diff = __fsub_rn(ev, zv);
    out[o] = __fadd_rn(zv, diff);
    const float sq = __fmul_rn(diff, diff);

    double v = (double)sq;
    #pragma unroll
    for (int off = 16; off > 0; off >>= 1)
        v += __shfl_down_sync(0xffffffffu, v, off);
    __shared__ double ws[8];
    if ((threadIdx.x & 31) == 0) ws[threadIdx.x >> 5] = v;
    __syncthreads();
    if (threadIdx.x == 0) {
        double s = 0.0;
        #pragma unroll
        for (int wv = 0; wv < 8; ++wv) s += ws[wv];
        atomicAdd(&g_loss_sum, s);
    }
}

__global__ void vq_finalize_kernel(float* __restrict__ out) {
    float m = (float)(g_loss_sum / (double)ZQ_SIZE);
    out[ZQ_SIZE] = __fadd_rn(__fmul_rn(BETA_F, m), m);
}

// ============================================================================
extern "C" void kernel_launch(void* const* d_in, const int* in_sizes, int n_in,
                              void* d_out, int out_size)
{
    const float* z   = (const float*)d_in[0];
    const float* emb = (const float*)d_in[1];
    float* out = (float*)d_out;

    cudaFuncSetAttribute(vq_gemm_screen,
                         cudaFuncAttributeMaxDynamicSharedMemorySize, GEMM_SMEM);
    cudaFuncSetAttribute(vq_passb,
                         cudaFuncAttributeMaxDynamicSharedMemorySize, PB_SMEM);

    vq_e16_kernel<<<NE * EDIM / 256, 256>>>(emb);
    vq_z16_kernel<<<dim3(32, 8, 16), dim3(32, 8)>>>(z);
    vq_zsq_kernel<<<N_ROWS / 256, 256>>>(z);

    vq_gemm_screen<<<GRID_GEMM, 256, GEMM_SMEM>>>();

    vq_passb<<<N_ROWS / 8, 256, PB_SMEM>>>(z, emb, out + ZQ_SIZE + 1);

    vq_out_kernel<<<ZQ_SIZE / 256, 256>>>(z, emb, out);
    vq_finalize_kernel<<<1, 1>>>(out);
}

// round 16
// speedup vs baseline: 42.0129x; 1.5541x over previous
#include <cuda_runtime.h>
#include <cuda_fp16.h>
#include <cstdint>

// ============================================================================
// VectorQuantizer — HMMA fp16 screen + exact fp32 verify.
// Round-16 deltas (numerics untouched, rel_err 0.0 lineage):
//  1. passB dot reads a pre-transposed fp32 codebook g_embT[k][code]
//     (same bits, same ascending-k fmaf chain) -> coalesced: 4 sectors/instr
//     instead of 32 lines/instr.
//  2. GEMM sB staging via cp.async double-buffer (prefetch ct+1 during
//     compute of ct); contiguous item ranges so A restages ~2x/CTA not 7x.
// ============================================================================

#define N_ROWS   16384
#define NE       8192
#define EDIM     256
#define ZQ_SIZE  4194304
#define BETA_F   1.0f
#define MARGIN_F 4.0e-4f
#define DSCALE   (-0.0001220703125f)   /* -2^-13 */

__device__ __align__(16) __half g_z16[N_ROWS * EDIM];   // [row][k]
__device__ __align__(16) __half g_e16[NE * EDIM];       // [code][k], * 2^14
__device__ __align__(16) float  g_embT[EDIM * NE];      // [k][code] fp32 (exact)
__device__ __align__(16) float  g_cmin[N_ROWS * 1024];  // per 8-code chunk
__device__ float  g_zsq[N_ROWS];
__device__ int    g_minidx[N_ROWS];
__device__ double g_loss_sum;

__device__ __forceinline__ uint32_t smem_u32(const void* p) {
    uint32_t a;
    asm("{ .reg .u64 t; cvta.to.shared.u64 t, %1; cvt.u32.u64 %0, t; }" : "=r"(a) : "l"(p));
    return a;
}
__device__ __forceinline__ void cp16(uint32_t s, const void* g) {
    asm volatile("cp.async.cg.shared.global [%0], [%1], 16;" :: "r"(s), "l"(g));
}
#define CP_COMMIT() asm volatile("cp.async.commit_group;" ::: "memory")
#define CP_WAIT0()  asm volatile("cp.async.wait_group 0;" ::: "memory")

__device__ __forceinline__ void ldsm_x4(uint32_t r[4], uint32_t addr) {
    asm volatile("ldmatrix.sync.aligned.m8n8.x4.shared.b16 {%0,%1,%2,%3}, [%4];"
                 : "=r"(r[0]), "=r"(r[1]), "=r"(r[2]), "=r"(r[3]) : "r"(addr));
}
__device__ __forceinline__ void mma16816(float c[4], const uint32_t a[4], const uint32_t b[2]) {
    asm volatile("mma.sync.aligned.m16n8k16.row.col.f32.f16.f16.f32 "
                 "{%0,%1,%2,%3}, {%4,%5,%6,%7}, {%8,%9}, {%0,%1,%2,%3};"
                 : "+f"(c[0]), "+f"(c[1]), "+f"(c[2]), "+f"(c[3])
                 : "r"(a[0]), "r"(a[1]), "r"(a[2]), "r"(a[3]), "r"(b[0]), "r"(b[1]));
}

// ============================================================================
// Preprocessing
// ============================================================================
__global__ __launch_bounds__(256) void vq_e16_kernel(const float* __restrict__ emb) {
    int i = blockIdx.x * 256 + threadIdx.x;
    g_e16[i] = __float2half_rn(emb[i] * 16384.0f);   // exact pow2 scale
    if (blockIdx.x == 0 && threadIdx.x == 0) g_loss_sum = 0.0;
}

// emb [code][k] -> g_embT [k][code], exact fp32 copy
__global__ __launch_bounds__(256) void vq_etr_kernel(const float* __restrict__ emb) {
    __shared__ float t[32][33];
    const int c0 = blockIdx.x * 32, k0 = blockIdx.y * 32;
    const int tx = threadIdx.x, ty = threadIdx.y;   // (32, 8)
    #pragma unroll
    for (int i = 0; i < 4; ++i)
        t[ty + i * 8][tx] = emb[(size_t)(c0 + ty + i * 8) * 256 + k0 + tx];
    __syncthreads();
    #pragma unroll
    for (int i = 0; i < 4; ++i)
        g_embT[(size_t)(k0 + ty + i * 8) * NE + c0 + tx] = t[tx][ty + i * 8];
}

__global__ __launch_bounds__(256) void vq_z16_kernel(const float* __restrict__ z) {
    __shared__ float t[32][33];
    const int b = blockIdx.z, k0 = blockIdx.y * 32, hw0 = blockIdx.x * 32;
    const int tx = threadIdx.x, ty = threadIdx.y;   // (32, 8)
    #pragma unroll
    for (int i = 0; i < 4; ++i) {
        int kl = ty + i * 8;
        t[kl][tx] = z[(size_t)b * 262144 + (size_t)(k0 + kl) * 1024 + hw0 + tx];
    }
    __syncthreads();
    #pragma unroll
    for (int i = 0; i < 4; ++i) {
        int hwl = ty + i * 8;
        g_z16[((size_t)b * 1024 + hw0 + hwl) * 256 + k0 + tx] = __float2half_rn(t[tx][hwl]);
    }
}

__global__ __launch_bounds__(256) void vq_zsq_kernel(const float* __restrict__ z) {
    const int n = blockIdx.x * 256 + threadIdx.x;
    const int b = n >> 10, hw = n & 1023;
    float s = 0.0f;
    for (int k = 0; k < 256; ++k) {
        float v = z[(size_t)b * 262144 + (size_t)k * 1024 + hw];
        s = __fadd_rn(s, __fmul_rn(v, v));
    }
    g_zsq[n] = s;
}

// ============================================================================
// Screen GEMM: persistent contiguous item ranges; sB cp.async double-buffered.
// item = rt*8 + cs; rt = 128-row tile, cs = 1024-code slice.
// smem: sA 67584 | sB0 67584 | sB1 67584 = 202752 B
// ============================================================================
#define PITCH_B   528
#define TILE_BYTES (128 * PITCH_B)      // 67584
#define GEMM_SMEM  (3 * TILE_BYTES)     // 202752
#define GRID_GEMM  152
#define N_ITEMS    1024

__global__ __launch_bounds__(256, 1) void vq_gemm_screen() {
    extern __shared__ char sm[];
    char* sA = sm;
    const uint32_t sAu = smem_u32(sA);
    const uint32_t sBu[2] = { sAu + TILE_BYTES, sAu + 2 * TILE_BYTES };
    const int tid  = threadIdx.x;
    const int warp = tid >> 5, lane = tid & 31;
    const int wm = warp & 3;
    const int wn = warp >> 2;
    const int q  = lane >> 2;

    const uint32_t aBase = sAu
        + (uint32_t)(wm * 32 + (lane & 15)) * PITCH_B + (uint32_t)(lane >> 4) * 16;
    const uint32_t bOff =
          (uint32_t)(wn * 64 + ((lane >> 4) << 3) + (lane & 7)) * PITCH_B
        + (uint32_t)((lane >> 3) & 1) * 16;

    // per-thread staging coords (same for A and B stagers)
    const int srow = tid >> 1;                 // 2 threads per 128-half row... no:
    (void)srow;

    auto stageB = [&](uint32_t dst, int gct) {
        #pragma unroll
        for (int it = 0; it < 16; ++it) {
            int idx = it * 256 + tid;
            int r = idx >> 5, c = idx & 31;
            cp16(dst + (uint32_t)(r * PITCH_B + c * 16),
                 g_e16 + (size_t)(gct * 128 + r) * 256 + c * 8);
        }
    };

    const int s = (blockIdx.x * N_ITEMS) / GRID_GEMM;
    const int e = ((blockIdx.x + 1) * N_ITEMS) / GRID_GEMM;

    int cur_rt = -1;
    float zsq4[4];

    for (int item = s; item < e; ++item) {
        const int rt = item >> 3;
        const int cs = item & 7;
        const int row0 = rt * 128;

        if (rt != cur_rt) {
            __syncthreads();   // prior compute done reading sA
            #pragma unroll
            for (int it = 0; it < 16; ++it) {
                int idx = it * 256 + tid;
                int r = idx >> 5, c = idx & 31;
                *(uint4*)(sA + r * PITCH_B + c * 16) =
                    *(const uint4*)(g_z16 + (size_t)(row0 + r) * 256 + c * 8);
            }
            cur_rt = rt;
            if ((lane & 3) == 0) {
                #pragma unroll
                for (int t = 0; t < 4; ++t)
                    zsq4[t] = g_zsq[row0 + wm * 32 + t * 8 + q];
            }
        }

        // prefetch B for ct=0 of this item (buffers safe: last read 2 cts ago)
        stageB(sBu[0], cs * 8);
        CP_COMMIT();

        for (int ct = 0; ct < 8; ++ct) {
            const int gct = cs * 8 + ct;
            const uint32_t bufu = sBu[ct & 1];

            CP_WAIT0();        // data for ct landed
            __syncthreads();   // all threads past prior compute; data visible

            if (ct + 1 < 8) {  // prefetch ct+1 into the other buffer
                stageB(sBu[(ct + 1) & 1], gct + 1);
                CP_COMMIT();
            }

            float acc[2][8][4];
            #pragma unroll
            for (int mt = 0; mt < 2; ++mt)
                #pragma unroll
                for (int nt = 0; nt < 8; ++nt)
                    #pragma unroll
                    for (int i = 0; i < 4; ++i) acc[mt][nt][i] = 0.0f;

            #pragma unroll
            for (int ks = 0; ks < 16; ++ks) {
                uint32_t a[2][4];
                #pragma unroll
                for (int mt = 0; mt < 2; ++mt)
                    ldsm_x4(a[mt], aBase + (uint32_t)mt * (16 * PITCH_B) + (uint32_t)ks * 32);
                uint32_t b[8][2];
                #pragma unroll
                for (int np = 0; np < 4; ++np) {
                    uint32_t r4[4];
                    ldsm_x4(r4, bufu + bOff + (uint32_t)np * (16 * PITCH_B) + (uint32_t)ks * 32);
                    b[2 * np][0] = r4[0]; b[2 * np][1] = r4[1];
                    b[2 * np + 1][0] = r4[2]; b[2 * np + 1][1] = r4[3];
                }
                #pragma unroll
                for (int mt = 0; mt < 2; ++mt)
                    #pragma unroll
                    for (int nt = 0; nt < 8; ++nt)
                        mma16816(acc[mt][nt], a[mt], b[nt]);
            }

            // epilogue: per-(row, 8-code chunk) min (validated round 13)
            #pragma unroll
            for (int mt = 0; mt < 2; ++mt) {
                #pragma unroll
                for (int nt = 0; nt < 8; ++nt) {
                    float mA = fmaxf(acc[mt][nt][0], acc[mt][nt][1]);
                    float mB = fmaxf(acc[mt][nt][2], acc[mt][nt][3]);
                    mA = fmaxf(mA, __shfl_xor_sync(0xffffffffu, mA, 1));
                    mA = fmaxf(mA, __shfl_xor_sync(0xffffffffu, mA, 2));
                    mB = fmaxf(mB, __shfl_xor_sync(0xffffffffu, mB, 1));
                    mB = fmaxf(mB, __shfl_xor_sync(0xffffffffu, mB, 2));
                    if ((lane & 3) == 0) {
                        const int ch = gct * 16 + wn * 8 + nt;
                        const int rowA = row0 + wm * 32 + mt * 16 + q;
                        g_cmin[(size_t)rowA * 1024 + ch] =
                            __fmaf_rn(mA, DSCALE, zsq4[mt * 2]);
                        g_cmin[(size_t)(rowA + 8) * 1024 + ch] =
                            __fmaf_rn(mB, DSCALE, zsq4[mt * 2 + 1]);
                    }
                }
            }
        }
    }
}

// ============================================================================
// Pass B: high-occupancy exact fp32 verify; dot reads g_embT (coalesced).
// 256 threads = 8 warps = 8 rows/block; smem 8.3 KB.
// ============================================================================
#define PB_SMEM (8 * 256 * 4 + 8 * 4 * 4)

__global__ __launch_bounds__(256) void vq_passb(
    const float* __restrict__ z,
    float* __restrict__ out_idx_f)
{
    extern __shared__ float smf[];
    const int w = threadIdx.x >> 5, lane = threadIdx.x & 31;
    float* zsm = smf + w * 256;
    int*   slots = (int*)(smf + 8 * 256) + w * 4;
    const int r = blockIdx.x * 8 + w;
    const int b = r >> 10, hw = r & 1023;

    const float* cm = g_cmin + (size_t)r * 1024;

    float cv[32];
    #pragma unroll
    for (int g = 0; g < 8; ++g) {
        float4 v = *(const float4*)(cm + g * 128 + lane * 4);
        cv[g * 4 + 0] = v.x; cv[g * 4 + 1] = v.y;
        cv[g * 4 + 2] = v.z; cv[g * 4 + 3] = v.w;
    }
    float rm = cv[0];
    #pragma unroll
    for (int i = 1; i < 32; ++i) rm = fminf(rm, cv[i]);
    #pragma unroll
    for (int off = 16; off > 0; off >>= 1)
        rm = fminf(rm, __shfl_xor_sync(0xffffffffu, rm, off));
    const float thr = rm + MARGIN_F;

    #pragma unroll
    for (int kk = 0; kk < 8; ++kk)
        zsm[kk * 32 + lane] = z[(size_t)b * 262144 + (size_t)(kk * 32 + lane) * 1024 + hw];
    __syncwarp();
    const float zsqv = g_zsq[r];

    float bd = 3.4e38f;
    int   bi = 0x7fffffff;
    int   ns = 0;

    auto flush = [&](int n) {
        __syncwarp();
        if (lane < n * 8) {
            const int code = slots[lane >> 3] * 8 + (lane & 7);
            float dacc = 0.0f;
            #pragma unroll 8
            for (int k = 0; k < 256; ++k)
                dacc = __fmaf_rn(zsm[k], __ldg(g_embT + (size_t)k * NE + code), dacc);
            float d = __fmaf_rn(-2.0f, dacc, zsqv);
            if (d < bd || (d == bd && code < bi)) { bd = d; bi = code; }
        }
        __syncwarp();
    };

    #pragma unroll
    for (int g = 0; g < 8; ++g) {
        #pragma unroll
        for (int ss = 0; ss < 4; ++ss) {
            unsigned m = __ballot_sync(0xffffffffu, cv[g * 4 + ss] <= thr);
            while (m) {
                int src = __ffs(m) - 1;
                m &= m - 1;
                if (lane == 0) slots[ns] = g * 128 + src * 4 + ss;
                ns++;
                if (ns == 4) { flush(4); ns = 0; }
            }
        }
    }
    if (ns) flush(ns);

    #pragma unroll
    for (int off = 16; off > 0; off >>= 1) {
        float od = __shfl_down_sync(0xffffffffu, bd, off);
        int   oi = __shfl_down_sync(0xffffffffu, bi, off);
        if (od < bd || (od == bd && oi < bi)) { bd = od; bi = oi; }
    }
    if (lane == 0) {
        g_minidx[r]  = bi;
        out_idx_f[r] = (float)bi;
    }
}

// ============================================================================
// Output: straight-through z_q + loss (validated verbatim)
// ============================================================================
__global__ __launch_bounds__(256) void vq_out_kernel(
    const float* __restrict__ z,
    const float* __restrict__ emb,
    float* __restrict__ out)
{
    const int o = blockIdx.x * 256 + threadIdx.x;
    const int c = (o >> 10) & 255;
    const int n = ((o >> 18) << 10) | (o & 1023);

    const int idx = g_minidx[n];
    const float zv = z[o];
    const float ev = __ldg(&emb[(size_t)idx * 256 + c]);
    const float diff = __fsub_rn(ev, zv);
    out[o] = __fadd_rn(zv, diff);
    const float sq = __fmul_rn(diff, diff);

    double v = (double)sq;
    #pragma unroll
    for (int off = 16; off > 0; off >>= 1)
        v += __shfl_down_sync(0xffffffffu, v, off);
    __shared__ double ws[8];
    if ((threadIdx.x & 31) == 0) ws[threadIdx.x >> 5] = v;
    __syncthreads();
    if (threadIdx.x == 0) {
        double sdd = 0.0;
        #pragma unroll
        for (int wv = 0; wv < 8; ++wv) sdd += ws[wv];
        atomicAdd(&g_loss_sum, sdd);
    }
}

__global__ void vq_finalize_kernel(float* __restrict__ out) {
    float m = (float)(g_loss_sum / (double)ZQ_SIZE);
    out[ZQ_SIZE] = __fadd_rn(__fmul_rn(BETA_F, m), m);
}

// ============================================================================
extern "C" void kernel_launch(void* const* d_in, const int* in_sizes, int n_in,
                              void* d_out, int out_size)
{
    const float* z   = (const float*)d_in[0];
    const float* emb = (const float*)d_in[1];
    float* out = (float*)d_out;

    cudaFuncSetAttribute(vq_gemm_screen,
                         cudaFuncAttributeMaxDynamicSharedMemorySize, GEMM_SMEM);
    cudaFuncSetAttribute(vq_passb,
                         cudaFuncAttributeMaxDynamicSharedMemorySize, PB_SMEM);

    vq_e16_kernel<<<NE * EDIM / 256, 256>>>(emb);
    vq_etr_kernel<<<dim3(256, 8), dim3(32, 8)>>>(emb);
    vq_z16_kernel<<<dim3(32, 8, 16), dim3(32, 8)>>>(z);
    vq_zsq_kernel<<<N_ROWS / 256, 256>>>(z);

    vq_gemm_screen<<<GRID_GEMM, 256, GEMM_SMEM>>>();

    vq_passb<<<N_ROWS / 8, 256, PB_SMEM>>>(z, out + ZQ_SIZE + 1);

    vq_out_kernel<<<ZQ_SIZE / 256, 256>>>(z, emb, out);
    vq_finalize_kernel<<<1, 1>>>(out);
}

// round 17
// speedup vs baseline: 45.3131x; 1.0786x over previous
#include <cuda_runtime.h>
#include <cuda_fp16.h>
#include <cstdint>

// ============================================================================
// VectorQuantizer — HMMA fp16 screen + exact fp32 verify (rel_err 0.0 lineage).
// Round-17 deltas:
//  1. GEMM 512 threads (16 warps), warp tile 32x32 (4wm x 4wn): 4 warps/SMSP
//     hide LDSM latency inside the mma-issue floor (round-16: 2/SMSP, serial).
//  2. vq_out float4-vectorized.  3. e16 + embT fused (one emb read).
// ============================================================================

#define N_ROWS   16384
#define NE       8192
#define EDIM     256
#define ZQ_SIZE  4194304
#define BETA_F   1.0f
#define MARGIN_F 4.0e-4f
#define DSCALE   (-0.0001220703125f)   /* -2^-13 */

__device__ __align__(16) __half g_z16[N_ROWS * EDIM];   // [row][k]
__device__ __align__(16) __half g_e16[NE * EDIM];       // [code][k], * 2^14
__device__ __align__(16) float  g_embT[EDIM * NE];      // [k][code] fp32 (exact)
__device__ __align__(16) float  g_cmin[N_ROWS * 1024];  // per 8-code chunk
__device__ float  g_zsq[N_ROWS];
__device__ int    g_minidx[N_ROWS];
__device__ double g_loss_sum;

__device__ __forceinline__ uint32_t smem_u32(const void* p) {
    uint32_t a;
    asm("{ .reg .u64 t; cvta.to.shared.u64 t, %1; cvt.u32.u64 %0, t; }" : "=r"(a) : "l"(p));
    return a;
}
__device__ __forceinline__ void cp16(uint32_t s, const void* g) {
    asm volatile("cp.async.cg.shared.global [%0], [%1], 16;" :: "r"(s), "l"(g));
}
#define CP_COMMIT() asm volatile("cp.async.commit_group;" ::: "memory")
#define CP_WAIT0()  asm volatile("cp.async.wait_group 0;" ::: "memory")

__device__ __forceinline__ void ldsm_x4(uint32_t r[4], uint32_t addr) {
    asm volatile("ldmatrix.sync.aligned.m8n8.x4.shared.b16 {%0,%1,%2,%3}, [%4];"
                 : "=r"(r[0]), "=r"(r[1]), "=r"(r[2]), "=r"(r[3]) : "r"(addr));
}
__device__ __forceinline__ void mma16816(float c[4], const uint32_t a[4], const uint32_t b[2]) {
    asm volatile("mma.sync.aligned.m16n8k16.row.col.f32.f16.f16.f32 "
                 "{%0,%1,%2,%3}, {%4,%5,%6,%7}, {%8,%9}, {%0,%1,%2,%3};"
                 : "+f"(c[0]), "+f"(c[1]), "+f"(c[2]), "+f"(c[3])
                 : "r"(a[0]), "r"(a[1]), "r"(a[2]), "r"(a[3]), "r"(b[0]), "r"(b[1]));
}

// ============================================================================
// Preprocessing
// ============================================================================
// emb [code][k] -> g_e16 [code][k] (*2^14, exact) AND g_embT [k][code] (fp32)
__global__ __launch_bounds__(256) void vq_eprep_kernel(const float* __restrict__ emb) {
    __shared__ float t[32][33];
    const int c0 = blockIdx.x * 32, k0 = blockIdx.y * 32;
    const int tx = threadIdx.x, ty = threadIdx.y;   // (32, 8)
    #pragma unroll
    for (int i = 0; i < 4; ++i) {
        float v = emb[(size_t)(c0 + ty + i * 8) * 256 + k0 + tx];
        t[ty + i * 8][tx] = v;
        g_e16[(size_t)(c0 + ty + i * 8) * 256 + k0 + tx] = __float2half_rn(v * 16384.0f);
    }
    __syncthreads();
    #pragma unroll
    for (int i = 0; i < 4; ++i)
        g_embT[(size_t)(k0 + ty + i * 8) * NE + c0 + tx] = t[tx][ty + i * 8];
    if (blockIdx.x == 0 && blockIdx.y == 0 && tx == 0 && ty == 0) g_loss_sum = 0.0;
}

__global__ __launch_bounds__(256) void vq_z16_kernel(const float* __restrict__ z) {
    __shared__ float t[32][33];
    const int b = blockIdx.z, k0 = blockIdx.y * 32, hw0 = blockIdx.x * 32;
    const int tx = threadIdx.x, ty = threadIdx.y;   // (32, 8)
    #pragma unroll
    for (int i = 0; i < 4; ++i) {
        int kl = ty + i * 8;
        t[kl][tx] = z[(size_t)b * 262144 + (size_t)(k0 + kl) * 1024 + hw0 + tx];
    }
    __syncthreads();
    #pragma unroll
    for (int i = 0; i < 4; ++i) {
        int hwl = ty + i * 8;
        g_z16[((size_t)b * 1024 + hw0 + hwl) * 256 + k0 + tx] = __float2half_rn(t[tx][hwl]);
    }
}

__global__ __launch_bounds__(256) void vq_zsq_kernel(const float* __restrict__ z) {
    const int n = blockIdx.x * 256 + threadIdx.x;
    const int b = n >> 10, hw = n & 1023;
    float s = 0.0f;
    for (int k = 0; k < 256; ++k) {
        float v = z[(size_t)b * 262144 + (size_t)k * 1024 + hw];
        s = __fadd_rn(s, __fmul_rn(v, v));
    }
    g_zsq[n] = s;
}

// ============================================================================
// Screen GEMM: 512 threads, 16 warps (warp tile 32 rows x 32 codes),
// persistent contiguous item ranges, sB cp.async double-buffered.
// item = rt*8 + cs; smem: sA 67584 | sB0 67584 | sB1 67584 = 202752 B
// ============================================================================
#define PITCH_B   528
#define TILE_BYTES (128 * PITCH_B)      // 67584
#define GEMM_SMEM  (3 * TILE_BYTES)     // 202752
#define GRID_GEMM  152
#define N_ITEMS    1024

__global__ __launch_bounds__(512, 1) void vq_gemm_screen() {
    extern __shared__ char sm[];
    char* sA = sm;
    const uint32_t sAu = smem_u32(sA);
    const uint32_t sBu0 = sAu + TILE_BYTES;
    const uint32_t sBu1 = sAu + 2 * TILE_BYTES;
    const int tid  = threadIdx.x;
    const int warp = tid >> 5, lane = tid & 31;
    const int wm = warp & 3;          // 32 rows
    const int wn = warp >> 2;         // 0..3 -> 32 codes
    const int q  = lane >> 2;

    const uint32_t aBase = sAu
        + (uint32_t)(wm * 32 + (lane & 15)) * PITCH_B + (uint32_t)(lane >> 4) * 16;
    const uint32_t bOff =
          (uint32_t)(wn * 32 + ((lane >> 4) << 3) + (lane & 7)) * PITCH_B
        + (uint32_t)((lane >> 3) & 1) * 16;

    auto stageB = [&](uint32_t dst, int gct) {
        #pragma unroll
        for (int it = 0; it < 8; ++it) {
            int idx = it * 512 + tid;
            int r = idx >> 5, c = idx & 31;
            cp16(dst + (uint32_t)(r * PITCH_B + c * 16),
                 g_e16 + (size_t)(gct * 128 + r) * 256 + c * 8);
        }
    };

    const int s = (blockIdx.x * N_ITEMS) / GRID_GEMM;
    const int e = ((blockIdx.x + 1) * N_ITEMS) / GRID_GEMM;

    int cur_rt = -1;
    float zsq4[4];

    for (int item = s; item < e; ++item) {
        const int rt = item >> 3;
        const int cs = item & 7;
        const int row0 = rt * 128;

        if (rt != cur_rt) {
            __syncthreads();   // prior compute done reading sA
            #pragma unroll
            for (int it = 0; it < 8; ++it) {
                int idx = it * 512 + tid;
                int r = idx >> 5, c = idx & 31;
                *(uint4*)(sA + r * PITCH_B + c * 16) =
                    *(const uint4*)(g_z16 + (size_t)(row0 + r) * 256 + c * 8);
            }
            cur_rt = rt;
            if ((lane & 3) == 0) {
                #pragma unroll
                for (int t = 0; t < 4; ++t)
                    zsq4[t] = g_zsq[row0 + wm * 32 + t * 8 + q];
            }
        }

        stageB(sBu0, cs * 8);
        CP_COMMIT();

        for (int ct = 0; ct < 8; ++ct) {
            const int gct = cs * 8 + ct;
            const uint32_t bufu = (ct & 1) ? sBu1 : sBu0;

            CP_WAIT0();
            __syncthreads();

            if (ct + 1 < 8) {
                stageB((ct & 1) ? sBu0 : sBu1, gct + 1);
                CP_COMMIT();
            }

            float acc[2][4][4];
            #pragma unroll
            for (int mt = 0; mt < 2; ++mt)
                #pragma unroll
                for (int nt = 0; nt < 4; ++nt)
                    #pragma unroll
                    for (int i = 0; i < 4; ++i) acc[mt][nt][i] = 0.0f;

            #pragma unroll
            for (int ks = 0; ks < 16; ++ks) {
                uint32_t a[2][4];
                #pragma unroll
                for (int mt = 0; mt < 2; ++mt)
                    ldsm_x4(a[mt], aBase + (uint32_t)mt * (16 * PITCH_B) + (uint32_t)ks * 32);
                uint32_t b[4][2];
                #pragma unroll
                for (int np = 0; np < 2; ++np) {
                    uint32_t r4[4];
                    ldsm_x4(r4, bufu + bOff + (uint32_t)np * (16 * PITCH_B) + (uint32_t)ks * 32);
                    b[2 * np][0] = r4[0]; b[2 * np][1] = r4[1];
                    b[2 * np + 1][0] = r4[2]; b[2 * np + 1][1] = r4[3];
                }
                #pragma unroll
                for (int mt = 0; mt < 2; ++mt)
                    #pragma unroll
                    for (int nt = 0; nt < 4; ++nt)
                        mma16816(acc[mt][nt], a[mt], b[nt]);
            }

            // epilogue: per-(row, 8-code chunk) min; ch = gct*16 + wn*4 + nt
            #pragma unroll
            for (int mt = 0; mt < 2; ++mt) {
                #pragma unroll
                for (int nt = 0; nt < 4; ++nt) {
                    float mA = fmaxf(acc[mt][nt][0], acc[mt][nt][1]);
                    float mB = fmaxf(acc[mt][nt][2], acc[mt][nt][3]);
                    mA = fmaxf(mA, __shfl_xor_sync(0xffffffffu, mA, 1));
                    mA = fmaxf(mA, __shfl_xor_sync(0xffffffffu, mA, 2));
                    mB = fmaxf(mB, __shfl_xor_sync(0xffffffffu, mB, 1));
                    mB = fmaxf(mB, __shfl_xor_sync(0xffffffffu, mB, 2));
                    if ((lane & 3) == 0) {
                        const int ch = gct * 16 + wn * 4 + nt;
                        const int rowA = row0 + wm * 32 + mt * 16 + q;
                        g_cmin[(size_t)rowA * 1024 + ch] =
                            __fmaf_rn(mA, DSCALE, zsq4[mt * 2]);
                        g_cmin[(size_t)(rowA + 8) * 1024 + ch] =
                            __fmaf_rn(mB, DSCALE, zsq4[mt * 2 + 1]);
                    }
                }
            }
        }
    }
}

// ============================================================================
// Pass B: high-occupancy exact fp32 verify (round-16 verbatim, rel_err 0.0)
// ============================================================================
#define PB_SMEM (8 * 256 * 4 + 8 * 4 * 4)

__global__ __launch_bounds__(256) void vq_passb(
    const float* __restrict__ z,
    float* __restrict__ out_idx_f)
{
    extern __shared__ float smf[];
    const int w = threadIdx.x >> 5, lane = threadIdx.x & 31;
    float* zsm = smf + w * 256;
    int*   slots = (int*)(smf + 8 * 256) + w * 4;
    const int r = blockIdx.x * 8 + w;
    const int b = r >> 10, hw = r & 1023;

    const float* cm = g_cmin + (size_t)r * 1024;

    float cv[32];
    #pragma unroll
    for (int g = 0; g < 8; ++g) {
        float4 v = *(const float4*)(cm + g * 128 + lane * 4);
        cv[g * 4 + 0] = v.x; cv[g * 4 + 1] = v.y;
        cv[g * 4 + 2] = v.z; cv[g * 4 + 3] = v.w;
    }
    float rm = cv[0];
    #pragma unroll
    for (int i = 1; i < 32; ++i) rm = fminf(rm, cv[i]);
    #pragma unroll
    for (int off = 16; off > 0; off >>= 1)
        rm = fminf(rm, __shfl_xor_sync(0xffffffffu, rm, off));
    const float thr = rm + MARGIN_F;

    #pragma unroll
    for (int kk = 0; kk < 8; ++kk)
        zsm[kk * 32 + lane] = z[(size_t)b * 262144 + (size_t)(kk * 32 + lane) * 1024 + hw];
    __syncwarp();
    const float zsqv = g_zsq[r];

    float bd = 3.4e38f;
    int   bi = 0x7fffffff;
    int   ns = 0;

    auto flush = [&](int n) {
        __syncwarp();
        if (lane < n * 8) {
            const int code = slots[lane >> 3] * 8 + (lane & 7);
            float dacc = 0.0f;
            #pragma unroll 8
            for (int k = 0; k < 256; ++k)
                dacc = __fmaf_rn(zsm[k], __ldg(g_embT + (size_t)k * NE + code), dacc);
            float d = __fmaf_rn(-2.0f, dacc, zsqv);
            if (d < bd || (d == bd && code < bi)) { bd = d; bi = code; }
        }
        __syncwarp();
    };

    #pragma unroll
    for (int g = 0; g < 8; ++g) {
        #pragma unroll
        for (int ss = 0; ss < 4; ++ss) {
            unsigned m = __ballot_sync(0xffffffffu, cv[g * 4 + ss] <= thr);
            while (m) {
                int src = __ffs(m) - 1;
                m &= m - 1;
                if (lane == 0) slots[ns] = g * 128 + src * 4 + ss;
                ns++;
                if (ns == 4) { flush(4); ns = 0; }
            }
        }
    }
    if (ns) flush(ns);

    #pragma unroll
    for (int off = 16; off > 0; off >>= 1) {
        float od = __shfl_down_sync(0xffffffffu, bd, off);
        int   oi = __shfl_down_sync(0xffffffffu, bi, off);
        if (od < bd || (od == bd && oi < bi)) { bd = od; bi = oi; }
    }
    if (lane == 0) {
        g_minidx[r]  = bi;
        out_idx_f[r] = (float)bi;
    }
}

// ============================================================================
// Output: straight-through z_q + loss, float4-vectorized (same element math)
// ============================================================================
__global__ __launch_bounds__(256) void vq_out_kernel(
    const float* __restrict__ z,
    const float* __restrict__ emb,
    float* __restrict__ out)
{
    const int o4 = (blockIdx.x * 256 + threadIdx.x) * 4;
    const int c  = (o4 >> 10) & 255;
    const int n0 = ((o4 >> 18) << 10) | (o4 & 1023);

    float4 zv = *(const float4*)(z + o4);
    float zr[4] = {zv.x, zv.y, zv.z, zv.w};
    float4 ov;
    float* op = &ov.x;
    double v = 0.0;
    #pragma unroll
    for (int j = 0; j < 4; ++j) {
        const int idx = g_minidx[n0 + j];
        const float ev = __ldg(&emb[(size_t)idx * 256 + c]);
        const float diff = __fsub_rn(ev, zr[j]);
        op[j] = __fadd_rn(zr[j], diff);
        v += (double)__fmul_rn(diff, diff);
    }
    *(float4*)(out + o4) = ov;

    #pragma unroll
    for (int off = 16; off > 0; off >>= 1)
        v += __shfl_down_sync(0xffffffffu, v, off);
    __shared__ double ws[8];
    if ((threadIdx.x & 31) == 0) ws[threadIdx.x >> 5] = v;
    __syncthreads();
    if (threadIdx.x == 0) {
        double sdd = 0.0;
        #pragma unroll
        for (int wv = 0; wv < 8; ++wv) sdd += ws[wv];
        atomicAdd(&g_loss_sum, sdd);
    }
}

__global__ void vq_finalize_kernel(float* __restrict__ out) {
    float m = (float)(g_loss_sum / (double)ZQ_SIZE);
    out[ZQ_SIZE] = __fadd_rn(__fmul_rn(BETA_F, m), m);
}

// ============================================================================
extern "C" void kernel_launch(void* const* d_in, const int* in_sizes, int n_in,
                              void* d_out, int out_size)
{
    const float* z   = (const float*)d_in[0];
    const float* emb = (const float*)d_in[1];
    float* out = (float*)d_out;

    cudaFuncSetAttribute(vq_gemm_screen,
                         cudaFuncAttributeMaxDynamicSharedMemorySize, GEMM_SMEM);
    cudaFuncSetAttribute(vq_passb,
                         cudaFuncAttributeMaxDynamicSharedMemorySize, PB_SMEM);

    vq_eprep_kernel<<<dim3(256, 8), dim3(32, 8)>>>(emb);
    vq_z16_kernel<<<dim3(32, 8, 16), dim3(32, 8)>>>(z);
    vq_zsq_kernel<<<N_ROWS / 256, 256>>>(z);

    vq_gemm_screen<<<GRID_GEMM, 512, GEMM_SMEM>>>();

    vq_passb<<<N_ROWS / 8, 256, PB_SMEM>>>(z, out + ZQ_SIZE + 1);

    vq_out_kernel<<<ZQ_SIZE / 1024, 256>>>(z, emb, out);
    vq_finalize_kernel<<<1, 1>>>(out);
}